// round 1
// baseline (speedup 1.0000x reference)
#include <cuda_runtime.h>

#define N_NODES  50000
#define N_EDGES  50000
#define NNZ      500000
#define N_GRAPHS 50
#define IN_C     128
#define HID      256
#define OUT_C    2

// ---------------- device scratch (static, allocation-free) ----------------
__device__ int   g_is64;
__device__ int   g_deg_node[N_NODES];
__device__ int   g_deg_edge[N_EDGES];
__device__ int   g_ptr_node[N_NODES + 1];
__device__ int   g_ptr_edge[N_EDGES + 1];
__device__ int   g_cur_node[N_NODES];
__device__ int   g_cur_edge[N_EDGES];
__device__ int   g_adj_node[NNZ];   // per node: incident hyperedge ids
__device__ int   g_adj_edge[NNZ];   // per hyperedge: incident node ids
__device__ float g_dinv[N_NODES];
__device__ float g_binv[N_EDGES];
__device__ int   g_gstart[N_GRAPHS + 1];
__device__ float g_xw[(size_t)N_NODES * HID];
__device__ float g_e [(size_t)N_EDGES * HID];
__device__ float g_h [(size_t)N_NODES * HID];
__device__ float g_pooled[N_GRAPHS * HID];

__device__ __forceinline__ long long load_idx(const void* p, long long i, int is64) {
    return is64 ? ((const long long*)p)[i] : (long long)((const int*)p)[i];
}

// ---------------- index dtype detection ----------------
// int64 values < 50000 -> every odd 32-bit word is 0. For int32, odd words are
// real edge indices (random in [0,50000)) -> virtually certainly nonzero.
__global__ void detect_kernel(const unsigned int* __restrict__ w) {
    __shared__ int any;
    if (threadIdx.x == 0) any = 0;
    __syncthreads();
    unsigned v = w[threadIdx.x * 2 + 1];
    if (v) atomicOr(&any, 1);
    __syncthreads();
    if (threadIdx.x == 0) g_is64 = any ? 0 : 1;
}

__global__ void zero_kernel() {
    int i = blockIdx.x * blockDim.x + threadIdx.x;
    if (i < N_NODES) g_deg_node[i] = 0;
    if (i < N_EDGES) g_deg_edge[i] = 0;
}

__global__ void count_kernel(const void* __restrict__ ei) {
    int i = blockIdx.x * blockDim.x + threadIdx.x;
    if (i >= NNZ) return;
    int is64 = g_is64;
    int r = (int)load_idx(ei, i, is64);
    int c = (int)load_idx(ei, (long long)NNZ + i, is64);
    atomicAdd(&g_deg_node[r], 1);
    atomicAdd(&g_deg_edge[c], 1);
}

// one block, 1024 threads: exclusive scan of 50000 ints (chunked + shared scan)
__device__ void scan_one(const int* __restrict__ deg, int* __restrict__ ptr,
                         int* __restrict__ cur, float* __restrict__ inv, int N) {
    __shared__ int part[1024];
    const int T = 1024;
    int t = threadIdx.x;
    int chunk = (N + T - 1) / T;
    int s = t * chunk;
    int e = min(s + chunk, N);
    if (s > N) s = N;
    int sum = 0;
    for (int i = s; i < e; i++) sum += deg[i];
    __syncthreads();           // protect shared reuse across calls
    part[t] = sum;
    __syncthreads();
    for (int off = 1; off < T; off <<= 1) {
        int v = (t >= off) ? part[t - off] : 0;
        __syncthreads();
        part[t] += v;
        __syncthreads();
    }
    int run = (t > 0) ? part[t - 1] : 0;
    for (int i = s; i < e; i++) {
        int d = deg[i];
        ptr[i] = run;
        cur[i] = run;
        inv[i] = (d > 0) ? 1.0f / (float)d : 0.0f;
        run += d;
    }
    if (t == 0) ptr[N] = part[T - 1];
    __syncthreads();
}

__global__ void scan_kernel() {
    scan_one(g_deg_node, g_ptr_node, g_cur_node, g_dinv, N_NODES);
    scan_one(g_deg_edge, g_ptr_edge, g_cur_edge, g_binv, N_EDGES);
}

__global__ void fill_kernel(const void* __restrict__ ei) {
    int i = blockIdx.x * blockDim.x + threadIdx.x;
    if (i >= NNZ) return;
    int is64 = g_is64;
    int r = (int)load_idx(ei, i, is64);
    int c = (int)load_idx(ei, (long long)NNZ + i, is64);
    int p = atomicAdd(&g_cur_edge[c], 1);
    g_adj_edge[p] = r;
    int q = atomicAdd(&g_cur_node[r], 1);
    g_adj_node[q] = c;
}

// batch is sorted: compute graph segment starts
__global__ void gstart_kernel(const void* __restrict__ batch) {
    int i = blockIdx.x * blockDim.x + threadIdx.x;
    if (i >= N_NODES) return;
    int is64 = g_is64;
    long long b  = load_idx(batch, i, is64);
    long long bp = (i == 0) ? -1 : load_idx(batch, i - 1, is64);
    if (b != bp)
        for (long long g = bp + 1; g <= b; g++) g_gstart[g] = i;
    if (i == N_NODES - 1)
        for (long long g = b + 1; g <= N_GRAPHS; g++) g_gstart[g] = N_NODES;
}

// ---------------- SGEMM: C[M,256] = A[M,K] * B[K,256] ----------------
// 128x128 tile, BK=8, 256 threads, 8x8 register tile (split 4+4 for bank-free LDS)
__global__ __launch_bounds__(256) void sgemm_kernel(
    const float* __restrict__ A, const float* __restrict__ B,
    float* __restrict__ C, int M, int K) {
    const int BM = 128, BN = 128, BK = 8;
    __shared__ float As[BK][BM];
    __shared__ float Bs[BK][BN];
    int bx = blockIdx.x;      // 0..1 (N=256)
    int by = blockIdx.y;
    int t  = threadIdx.x;
    int tx = t % 16, ty = t / 16;

    int arow = t >> 1;            // 0..127
    int acol = (t & 1) * 4;       // 0 or 4
    int brow = t >> 5;            // 0..7
    int bcol = (t & 31) * 4;      // 0..124

    float acc[8][8];
#pragma unroll
    for (int i = 0; i < 8; i++)
#pragma unroll
        for (int j = 0; j < 8; j++) acc[i][j] = 0.f;

    const float* Aptr = A + (size_t)by * BM * K;
    int grow = by * BM + arow;

    for (int k0 = 0; k0 < K; k0 += BK) {
        float4 av;
        if (grow < M) av = *(const float4*)(Aptr + (size_t)arow * K + k0 + acol);
        else          av = make_float4(0.f, 0.f, 0.f, 0.f);
        As[acol + 0][arow] = av.x;
        As[acol + 1][arow] = av.y;
        As[acol + 2][arow] = av.z;
        As[acol + 3][arow] = av.w;
        float4 bv = *(const float4*)(B + (size_t)(k0 + brow) * 256 + bx * BN + bcol);
        *(float4*)&Bs[brow][bcol] = bv;
        __syncthreads();
#pragma unroll
        for (int kk = 0; kk < BK; kk++) {
            float ra[8], rb[8];
            *(float4*)&ra[0] = *(const float4*)&As[kk][ty * 4];
            *(float4*)&ra[4] = *(const float4*)&As[kk][64 + ty * 4];
            *(float4*)&rb[0] = *(const float4*)&Bs[kk][tx * 4];
            *(float4*)&rb[4] = *(const float4*)&Bs[kk][64 + tx * 4];
#pragma unroll
            for (int i = 0; i < 8; i++)
#pragma unroll
                for (int j = 0; j < 8; j++) acc[i][j] += ra[i] * rb[j];
        }
        __syncthreads();
    }

#pragma unroll
    for (int i = 0; i < 8; i++) {
        int r = by * BM + ((i < 4) ? (ty * 4 + i) : (64 + ty * 4 + (i - 4)));
        if (r < M) {
            float4 v0 = make_float4(acc[i][0], acc[i][1], acc[i][2], acc[i][3]);
            float4 v1 = make_float4(acc[i][4], acc[i][5], acc[i][6], acc[i][7]);
            *(float4*)(C + (size_t)r * 256 + bx * BN + tx * 4)      = v0;
            *(float4*)(C + (size_t)r * 256 + bx * BN + 64 + tx * 4) = v1;
        }
    }
}

// ---------------- gathers (CSR, no atomics) ----------------
__global__ __launch_bounds__(256) void gather_edge_kernel() {
    int c = blockIdx.x, t = threadIdx.x;
    int s = g_ptr_edge[c], en = g_ptr_edge[c + 1];
    __shared__ int idx[256];
    float acc = 0.f;
    for (int base = s; base < en; base += 256) {
        int cnt = min(256, en - base);
        if (t < cnt) idx[t] = g_adj_edge[base + t];
        __syncthreads();
#pragma unroll 4
        for (int j = 0; j < cnt; j++)
            acc += g_xw[(size_t)idx[j] * HID + t];
        __syncthreads();
    }
    g_e[(size_t)c * HID + t] = acc * g_binv[c];
}

__global__ __launch_bounds__(256) void gather_node_kernel(const float* __restrict__ bias) {
    int n = blockIdx.x, t = threadIdx.x;
    int s = g_ptr_node[n], en = g_ptr_node[n + 1];
    __shared__ int idx[256];
    float acc = 0.f;
    for (int base = s; base < en; base += 256) {
        int cnt = min(256, en - base);
        if (t < cnt) idx[t] = g_adj_node[base + t];
        __syncthreads();
#pragma unroll 4
        for (int j = 0; j < cnt; j++)
            acc += g_e[(size_t)idx[j] * HID + t];
        __syncthreads();
    }
    float v = acc * g_dinv[n] + bias[t];
    g_h[(size_t)n * HID + t] = v > 0.f ? v : 0.f;
}

__global__ __launch_bounds__(256) void pool_kernel() {
    int g = blockIdx.x, t = threadIdx.x;
    int s = g_gstart[g], e = g_gstart[g + 1];
    float acc = 0.f;
    for (int i = s; i < e; i++) acc += g_h[(size_t)i * HID + t];
    int c = e - s;
    float inv = 1.0f / (float)max(c, 1);
    g_pooled[g * HID + t] = acc * inv;
}

__global__ __launch_bounds__(256) void mlp_kernel(
    const float* __restrict__ M1, const float* __restrict__ bM1,
    const float* __restrict__ M2, const float* __restrict__ bM2,
    float* __restrict__ out) {
    int g = blockIdx.x, t = threadIdx.x;
    __shared__ float p[HID];
    __shared__ float z[HID];
    __shared__ float red[HID];
    p[t] = g_pooled[g * HID + t];
    __syncthreads();
    float acc = bM1[t];
#pragma unroll 8
    for (int k = 0; k < HID; k++) acc += p[k] * M1[k * HID + t];
    z[t] = fmaxf(acc, 0.f);
    __syncthreads();
    for (int o = 0; o < OUT_C; o++) {
        red[t] = z[t] * M2[t * OUT_C + o];
        __syncthreads();
        for (int s = 128; s > 0; s >>= 1) {
            if (t < s) red[t] += red[t + s];
            __syncthreads();
        }
        if (t == 0) out[g * OUT_C + o] = red[0] + bM2[o];
        __syncthreads();
    }
}

// ---------------- launch ----------------
extern "C" void kernel_launch(void* const* d_in, const int* in_sizes, int n_in,
                              void* d_out, int out_size) {
    const float* x    = (const float*)d_in[0];
    const void*  ei   = d_in[1];
    const void*  batch= d_in[2];
    const float* W0   = (const float*)d_in[3];
    const float* b0   = (const float*)d_in[4];
    const float* W1   = (const float*)d_in[5];
    const float* b1   = (const float*)d_in[6];
    const float* W2   = (const float*)d_in[7];
    const float* b2   = (const float*)d_in[8];
    const float* M1   = (const float*)d_in[9];
    const float* bM1  = (const float*)d_in[10];
    const float* M2   = (const float*)d_in[11];
    const float* bM2  = (const float*)d_in[12];
    float* out = (float*)d_out;

    float* hptr  = nullptr;
    float* xwptr = nullptr;
    cudaGetSymbolAddress((void**)&hptr,  g_h);
    cudaGetSymbolAddress((void**)&xwptr, g_xw);

    detect_kernel<<<1, 256>>>((const unsigned int*)ei);
    zero_kernel<<<(N_NODES + 255) / 256, 256>>>();
    count_kernel<<<(NNZ + 255) / 256, 256>>>(ei);
    scan_kernel<<<1, 1024>>>();
    fill_kernel<<<(NNZ + 255) / 256, 256>>>(ei);
    gstart_kernel<<<(N_NODES + 255) / 256, 256>>>(batch);

    const float* Ws[3] = {W0, W1, W2};
    const float* bs[3] = {b0, b1, b2};
    const float* A = x;
    int K = IN_C;
    dim3 ggrid(2, (N_NODES + 127) / 128);
    for (int l = 0; l < 3; l++) {
        sgemm_kernel<<<ggrid, 256>>>(A, Ws[l], xwptr, N_NODES, K);
        gather_edge_kernel<<<N_EDGES, 256>>>();
        gather_node_kernel<<<N_NODES, 256>>>(bs[l]);
        A = hptr;
        K = HID;
    }
    pool_kernel<<<N_GRAPHS, 256>>>();
    mlp_kernel<<<N_GRAPHS, 256>>>(M1, bM1, M2, bM2, out);
}

// round 2
// speedup vs baseline: 1.7828x; 1.7828x over previous
#include <cuda_runtime.h>

#define N_NODES  50000
#define N_EDGES  50000
#define NNZ      500000
#define N_GRAPHS 50
#define IN_C     128
#define HID      256
#define OUT_C    2

#define SCAN_CHUNK 512
#define SCAN_NB    98    // 98*512 = 50176 >= 50000

// ---------------- device scratch (static, allocation-free) ----------------
__device__ int   g_is64;
__device__ int   g_deg_node[N_NODES];
__device__ int   g_deg_edge[N_EDGES];
__device__ int   g_ptr_node[N_NODES + 1];
__device__ int   g_ptr_edge[N_EDGES + 1];
__device__ int   g_cur_node[N_NODES];
__device__ int   g_cur_edge[N_EDGES];
__device__ int   g_adj_node[NNZ];   // per node: incident hyperedge ids
__device__ int   g_adj_edge[NNZ];   // per hyperedge: incident node ids
__device__ float g_dinv[N_NODES];
__device__ float g_binv[N_EDGES];
__device__ int   g_gstart[N_GRAPHS + 1];
__device__ int   g_part[2][SCAN_NB];      // block partial sums
__device__ int   g_part_ex[2][SCAN_NB];   // exclusive-scanned partials
__device__ float g_xw[(size_t)N_NODES * HID];
__device__ float g_e [(size_t)N_EDGES * HID];
__device__ float g_h [(size_t)N_NODES * HID];
__device__ float g_pooled[N_GRAPHS * HID];

__device__ __forceinline__ long long load_idx(const void* p, long long i, int is64) {
    return is64 ? ((const long long*)p)[i] : (long long)((const int*)p)[i];
}

// ---------------- index dtype detection ----------------
__global__ void detect_kernel(const unsigned int* __restrict__ w) {
    __shared__ int any;
    if (threadIdx.x == 0) any = 0;
    __syncthreads();
    unsigned v = w[threadIdx.x * 2 + 1];
    if (v) atomicOr(&any, 1);
    __syncthreads();
    if (threadIdx.x == 0) g_is64 = any ? 0 : 1;
}

__global__ void zero_kernel() {
    int i = blockIdx.x * blockDim.x + threadIdx.x;
    if (i < N_NODES) g_deg_node[i] = 0;
    if (i < N_EDGES) g_deg_edge[i] = 0;
}

__global__ void count_kernel(const void* __restrict__ ei) {
    int i = blockIdx.x * blockDim.x + threadIdx.x;
    if (i >= NNZ) return;
    int is64 = g_is64;
    int r = (int)load_idx(ei, i, is64);
    int c = (int)load_idx(ei, (long long)NNZ + i, is64);
    atomicAdd(&g_deg_node[r], 1);
    atomicAdd(&g_deg_edge[c], 1);
}

// ---------------- parallel exclusive scan, 3 phases ----------------
// phase 1: per-block partial sums. grid(SCAN_NB, 2), block 128
__global__ void scan_part_kernel() {
    int which = blockIdx.y;
    const int* deg = which ? g_deg_edge : g_deg_node;
    int start = blockIdx.x * SCAN_CHUNK;
    int t = threadIdx.x;
    int base = start + t * 4;
    int sum = 0;
#pragma unroll
    for (int j = 0; j < 4; j++) {
        int i = base + j;
        if (i < N_NODES) sum += deg[i];
    }
    __shared__ int s[128];
    s[t] = sum;
    __syncthreads();
    for (int off = 64; off > 0; off >>= 1) {
        if (t < off) s[t] += s[t + off];
        __syncthreads();
    }
    if (t == 0) g_part[which][blockIdx.x] = s[0];
}

// phase 2: scan the (2 x 98) partials. one block, 256 threads
__global__ void scan_mid_kernel() {
    __shared__ int s[256];
    int t = threadIdx.x;
    int which = t >> 7;         // 0..1
    int j = t & 127;            // 0..127
    s[t] = (j < SCAN_NB) ? g_part[which][j] : 0;
    __syncthreads();
    for (int off = 1; off < 128; off <<= 1) {
        int v = (j >= off) ? s[t - off] : 0;
        __syncthreads();
        s[t] += v;
        __syncthreads();
    }
    if (j < SCAN_NB)
        g_part_ex[which][j] = (j > 0) ? s[t - 1] : 0;
    if (t == 0) { g_ptr_node[N_NODES] = NNZ; g_ptr_edge[N_EDGES] = NNZ; }
}

// phase 3: local exclusive scan within each chunk + write. grid(SCAN_NB,2), block 128
__global__ void scan_write_kernel() {
    int which = blockIdx.y;
    const int* deg = which ? g_deg_edge : g_deg_node;
    int* ptr = which ? g_ptr_edge : g_ptr_node;
    int* cur = which ? g_cur_edge : g_cur_node;
    float* inv = which ? g_binv : g_dinv;
    int start = blockIdx.x * SCAN_CHUNK;
    int t = threadIdx.x;
    int base = start + t * 4;
    int d[4];
    int sum = 0;
#pragma unroll
    for (int j = 0; j < 4; j++) {
        int i = base + j;
        d[j] = (i < N_NODES) ? deg[i] : 0;
        sum += d[j];
    }
    __shared__ int s[128];
    s[t] = sum;
    __syncthreads();
    for (int off = 1; off < 128; off <<= 1) {
        int v = (t >= off) ? s[t - off] : 0;
        __syncthreads();
        s[t] += v;
        __syncthreads();
    }
    int run = g_part_ex[which][blockIdx.x] + ((t > 0) ? s[t - 1] : 0);
#pragma unroll
    for (int j = 0; j < 4; j++) {
        int i = base + j;
        if (i < N_NODES) {
            ptr[i] = run;
            cur[i] = run;
            inv[i] = (d[j] > 0) ? 1.0f / (float)d[j] : 0.0f;
            run += d[j];
        }
    }
}

__global__ void fill_kernel(const void* __restrict__ ei) {
    int i = blockIdx.x * blockDim.x + threadIdx.x;
    if (i >= NNZ) return;
    int is64 = g_is64;
    int r = (int)load_idx(ei, i, is64);
    int c = (int)load_idx(ei, (long long)NNZ + i, is64);
    int p = atomicAdd(&g_cur_edge[c], 1);
    g_adj_edge[p] = r;
    int q = atomicAdd(&g_cur_node[r], 1);
    g_adj_node[q] = c;
}

// batch is sorted: compute graph segment starts
__global__ void gstart_kernel(const void* __restrict__ batch) {
    int i = blockIdx.x * blockDim.x + threadIdx.x;
    if (i >= N_NODES) return;
    int is64 = g_is64;
    long long b  = load_idx(batch, i, is64);
    long long bp = (i == 0) ? -1 : load_idx(batch, i - 1, is64);
    if (b != bp)
        for (long long g = bp + 1; g <= b; g++) g_gstart[g] = i;
    if (i == N_NODES - 1)
        for (long long g = b + 1; g <= N_GRAPHS; g++) g_gstart[g] = N_NODES;
}

// ---------------- SGEMM: C[M,256] = A[M,K] * B[K,256] ----------------
// 128x128 tile, BK=16, double-buffered via register prefetch, 256 threads, 8x8 reg tile
__global__ __launch_bounds__(256) void sgemm_kernel(
    const float* __restrict__ A, const float* __restrict__ B,
    float* __restrict__ C, int M, int K) {
    const int BM = 128, BN = 128, BK = 16;
    __shared__ float As[2][BK][BM];
    __shared__ float Bs[2][BK][BN];
    int bx = blockIdx.x;      // 0..1
    int by = blockIdx.y;
    int t  = threadIdx.x;
    int tx = t % 16, ty = t / 16;

    int arow = t >> 1;            // 0..127
    int acol = (t & 1) * 8;       // 0 or 8
    int brow = t >> 4;            // 0..15
    int bcol = (t & 15) * 8;      // 0..120

    float acc[8][8];
#pragma unroll
    for (int i = 0; i < 8; i++)
#pragma unroll
        for (int j = 0; j < 8; j++) acc[i][j] = 0.f;

    int grow = by * BM + arow;
    bool aok = grow < M;
    const float* Arow = A + (size_t)grow * K;
    const float* Bp = B + bx * BN;

    float4 av0, av1, bv0, bv1;
    // prologue: load tile 0
    if (aok) {
        av0 = *(const float4*)(Arow + acol);
        av1 = *(const float4*)(Arow + acol + 4);
    } else { av0 = av1 = make_float4(0,0,0,0); }
    bv0 = *(const float4*)(Bp + (size_t)brow * 256 + bcol);
    bv1 = *(const float4*)(Bp + (size_t)brow * 256 + bcol + 4);

    int buf = 0;
    {
        float* as = &As[0][0][0];
        as[(acol+0)*BM+arow]=av0.x; as[(acol+1)*BM+arow]=av0.y;
        as[(acol+2)*BM+arow]=av0.z; as[(acol+3)*BM+arow]=av0.w;
        as[(acol+4)*BM+arow]=av1.x; as[(acol+5)*BM+arow]=av1.y;
        as[(acol+6)*BM+arow]=av1.z; as[(acol+7)*BM+arow]=av1.w;
        *(float4*)&Bs[0][brow][bcol]   = bv0;
        *(float4*)&Bs[0][brow][bcol+4] = bv1;
    }
    __syncthreads();

    for (int k0 = BK; k0 < K; k0 += BK) {
        // prefetch next tile into registers
        if (aok) {
            av0 = *(const float4*)(Arow + k0 + acol);
            av1 = *(const float4*)(Arow + k0 + acol + 4);
        }
        bv0 = *(const float4*)(Bp + (size_t)(k0 + brow) * 256 + bcol);
        bv1 = *(const float4*)(Bp + (size_t)(k0 + brow) * 256 + bcol + 4);

        // compute current buffer
#pragma unroll
        for (int kk = 0; kk < BK; kk++) {
            float ra[8], rb[8];
            *(float4*)&ra[0] = *(const float4*)&As[buf][kk][ty * 4];
            *(float4*)&ra[4] = *(const float4*)&As[buf][kk][64 + ty * 4];
            *(float4*)&rb[0] = *(const float4*)&Bs[buf][kk][tx * 4];
            *(float4*)&rb[4] = *(const float4*)&Bs[buf][kk][64 + tx * 4];
#pragma unroll
            for (int i = 0; i < 8; i++)
#pragma unroll
                for (int j = 0; j < 8; j++) acc[i][j] += ra[i] * rb[j];
        }

        // store prefetched tile into other buffer
        int nb = buf ^ 1;
        float* as = &As[nb][0][0];
        as[(acol+0)*BM+arow]=av0.x; as[(acol+1)*BM+arow]=av0.y;
        as[(acol+2)*BM+arow]=av0.z; as[(acol+3)*BM+arow]=av0.w;
        as[(acol+4)*BM+arow]=av1.x; as[(acol+5)*BM+arow]=av1.y;
        as[(acol+6)*BM+arow]=av1.z; as[(acol+7)*BM+arow]=av1.w;
        *(float4*)&Bs[nb][brow][bcol]   = bv0;
        *(float4*)&Bs[nb][brow][bcol+4] = bv1;
        __syncthreads();
        buf = nb;
    }

    // epilogue compute
#pragma unroll
    for (int kk = 0; kk < BK; kk++) {
        float ra[8], rb[8];
        *(float4*)&ra[0] = *(const float4*)&As[buf][kk][ty * 4];
        *(float4*)&ra[4] = *(const float4*)&As[buf][kk][64 + ty * 4];
        *(float4*)&rb[0] = *(const float4*)&Bs[buf][kk][tx * 4];
        *(float4*)&rb[4] = *(const float4*)&Bs[buf][kk][64 + tx * 4];
#pragma unroll
        for (int i = 0; i < 8; i++)
#pragma unroll
            for (int j = 0; j < 8; j++) acc[i][j] += ra[i] * rb[j];
    }

#pragma unroll
    for (int i = 0; i < 8; i++) {
        int r = by * BM + ((i < 4) ? (ty * 4 + i) : (64 + ty * 4 + (i - 4)));
        if (r < M) {
            float4 v0 = make_float4(acc[i][0], acc[i][1], acc[i][2], acc[i][3]);
            float4 v1 = make_float4(acc[i][4], acc[i][5], acc[i][6], acc[i][7]);
            *(float4*)(C + (size_t)r * 256 + bx * BN + tx * 4)      = v0;
            *(float4*)(C + (size_t)r * 256 + bx * BN + 64 + tx * 4) = v1;
        }
    }
}

// ---------------- gathers (CSR, no atomics), 1 warp per segment ----------------
// block = (32, 8): 8 segments per block, each lane holds two float4 (cols 4t, 128+4t)
__global__ __launch_bounds__(256) void gather_edge_kernel() {
    int seg = blockIdx.x * 8 + threadIdx.y;
    int t = threadIdx.x;
    __shared__ int idx[8][32];
    int s = g_ptr_edge[seg], en = g_ptr_edge[seg + 1];
    float4 a0 = make_float4(0,0,0,0), a1 = make_float4(0,0,0,0);
    for (int base = s; base < en; base += 32) {
        int cnt = min(32, en - base);
        if (t < cnt) idx[threadIdx.y][t] = g_adj_edge[base + t];
        __syncwarp();
#pragma unroll 2
        for (int j = 0; j < cnt; j++) {
            const float* row = g_xw + (size_t)idx[threadIdx.y][j] * HID;
            float4 v0 = *(const float4*)(row + 4 * t);
            float4 v1 = *(const float4*)(row + 128 + 4 * t);
            a0.x += v0.x; a0.y += v0.y; a0.z += v0.z; a0.w += v0.w;
            a1.x += v1.x; a1.y += v1.y; a1.z += v1.z; a1.w += v1.w;
        }
        __syncwarp();
    }
    float b = g_binv[seg];
    float* o = g_e + (size_t)seg * HID;
    *(float4*)(o + 4 * t)       = make_float4(a0.x*b, a0.y*b, a0.z*b, a0.w*b);
    *(float4*)(o + 128 + 4 * t) = make_float4(a1.x*b, a1.y*b, a1.z*b, a1.w*b);
}

__global__ __launch_bounds__(256) void gather_node_kernel(const float* __restrict__ bias) {
    int seg = blockIdx.x * 8 + threadIdx.y;
    int t = threadIdx.x;
    __shared__ int idx[8][32];
    int s = g_ptr_node[seg], en = g_ptr_node[seg + 1];
    float4 a0 = make_float4(0,0,0,0), a1 = make_float4(0,0,0,0);
    for (int base = s; base < en; base += 32) {
        int cnt = min(32, en - base);
        if (t < cnt) idx[threadIdx.y][t] = g_adj_node[base + t];
        __syncwarp();
#pragma unroll 2
        for (int j = 0; j < cnt; j++) {
            const float* row = g_e + (size_t)idx[threadIdx.y][j] * HID;
            float4 v0 = *(const float4*)(row + 4 * t);
            float4 v1 = *(const float4*)(row + 128 + 4 * t);
            a0.x += v0.x; a0.y += v0.y; a0.z += v0.z; a0.w += v0.w;
            a1.x += v1.x; a1.y += v1.y; a1.z += v1.z; a1.w += v1.w;
        }
        __syncwarp();
    }
    float d = g_dinv[seg];
    float4 c0 = *(const float4*)(bias + 4 * t);
    float4 c1 = *(const float4*)(bias + 128 + 4 * t);
    float* o = g_h + (size_t)seg * HID;
    *(float4*)(o + 4 * t) = make_float4(
        fmaxf(a0.x*d + c0.x, 0.f), fmaxf(a0.y*d + c0.y, 0.f),
        fmaxf(a0.z*d + c0.z, 0.f), fmaxf(a0.w*d + c0.w, 0.f));
    *(float4*)(o + 128 + 4 * t) = make_float4(
        fmaxf(a1.x*d + c1.x, 0.f), fmaxf(a1.y*d + c1.y, 0.f),
        fmaxf(a1.z*d + c1.z, 0.f), fmaxf(a1.w*d + c1.w, 0.f));
}

__global__ __launch_bounds__(256) void pool_kernel() {
    int g = blockIdx.x, t = threadIdx.x;
    int s = g_gstart[g], e = g_gstart[g + 1];
    float acc = 0.f;
    for (int i = s; i < e; i++) acc += g_h[(size_t)i * HID + t];
    int c = e - s;
    float inv = 1.0f / (float)max(c, 1);
    g_pooled[g * HID + t] = acc * inv;
}

__global__ __launch_bounds__(256) void mlp_kernel(
    const float* __restrict__ M1, const float* __restrict__ bM1,
    const float* __restrict__ M2, const float* __restrict__ bM2,
    float* __restrict__ out) {
    int g = blockIdx.x, t = threadIdx.x;
    __shared__ float p[HID];
    __shared__ float z[HID];
    __shared__ float red[HID];
    p[t] = g_pooled[g * HID + t];
    __syncthreads();
    float acc = bM1[t];
#pragma unroll 8
    for (int k = 0; k < HID; k++) acc += p[k] * M1[k * HID + t];
    z[t] = fmaxf(acc, 0.f);
    __syncthreads();
    for (int o = 0; o < OUT_C; o++) {
        red[t] = z[t] * M2[t * OUT_C + o];
        __syncthreads();
        for (int s = 128; s > 0; s >>= 1) {
            if (t < s) red[t] += red[t + s];
            __syncthreads();
        }
        if (t == 0) out[g * OUT_C + o] = red[0] + bM2[o];
        __syncthreads();
    }
}

// ---------------- launch ----------------
extern "C" void kernel_launch(void* const* d_in, const int* in_sizes, int n_in,
                              void* d_out, int out_size) {
    const float* x    = (const float*)d_in[0];
    const void*  ei   = d_in[1];
    const void*  batch= d_in[2];
    const float* W0   = (const float*)d_in[3];
    const float* b0   = (const float*)d_in[4];
    const float* W1   = (const float*)d_in[5];
    const float* b1   = (const float*)d_in[6];
    const float* W2   = (const float*)d_in[7];
    const float* b2   = (const float*)d_in[8];
    const float* M1   = (const float*)d_in[9];
    const float* bM1  = (const float*)d_in[10];
    const float* M2   = (const float*)d_in[11];
    const float* bM2  = (const float*)d_in[12];
    float* out = (float*)d_out;

    float* hptr  = nullptr;
    float* xwptr = nullptr;
    cudaGetSymbolAddress((void**)&hptr,  g_h);
    cudaGetSymbolAddress((void**)&xwptr, g_xw);

    detect_kernel<<<1, 256>>>((const unsigned int*)ei);
    zero_kernel<<<(N_NODES + 255) / 256, 256>>>();
    count_kernel<<<(NNZ + 255) / 256, 256>>>(ei);
    scan_part_kernel<<<dim3(SCAN_NB, 2), 128>>>();
    scan_mid_kernel<<<1, 256>>>();
    scan_write_kernel<<<dim3(SCAN_NB, 2), 128>>>();
    fill_kernel<<<(NNZ + 255) / 256, 256>>>(ei);
    gstart_kernel<<<(N_NODES + 255) / 256, 256>>>(batch);

    const float* Ws[3] = {W0, W1, W2};
    const float* bs[3] = {b0, b1, b2};
    const float* A = x;
    int K = IN_C;
    dim3 ggrid(2, (N_NODES + 127) / 128);
    dim3 gb(32, 8);
    for (int l = 0; l < 3; l++) {
        sgemm_kernel<<<ggrid, 256>>>(A, Ws[l], xwptr, N_NODES, K);
        gather_edge_kernel<<<N_EDGES / 8, gb>>>();
        gather_node_kernel<<<N_NODES / 8, gb>>>(bs[l]);
        A = hptr;
        K = HID;
    }
    pool_kernel<<<N_GRAPHS, 256>>>();
    mlp_kernel<<<N_GRAPHS, 256>>>(M1, bM1, M2, bM2, out);
}

// round 3
// speedup vs baseline: 2.2971x; 1.2884x over previous
#include <cuda_runtime.h>
#include <cuda_bf16.h>

#define N_NODES  50000
#define N_EDGES  50000
#define NNZ      500000
#define N_GRAPHS 50
#define IN_C     128
#define HID      256
#define OUT_C    2

#define SCAN_CHUNK 512
#define SCAN_NB    98    // 98*512 = 50176 >= 50000

// ---------------- device scratch (static, allocation-free) ----------------
__device__ int   g_is64;
__device__ int   g_deg_node[N_NODES];
__device__ int   g_deg_edge[N_EDGES];
__device__ int   g_ptr_node[N_NODES + 1];
__device__ int   g_ptr_edge[N_EDGES + 1];
__device__ int   g_cur_node[N_NODES];
__device__ int   g_cur_edge[N_EDGES];
__device__ int   g_adj_node[NNZ];
__device__ int   g_adj_edge[NNZ];
__device__ float g_dinv[N_NODES];
__device__ float g_binv[N_EDGES];
__device__ int   g_gstart[N_GRAPHS + 1];
__device__ int   g_part[2][SCAN_NB];
__device__ int   g_part_ex[2][SCAN_NB];
__device__ float g_xw[(size_t)N_NODES * HID];
__device__ float g_e [(size_t)N_EDGES * HID];
__device__ float g_h [(size_t)N_NODES * HID];
__device__ float g_pooled[N_GRAPHS * HID];

__device__ __forceinline__ long long load_idx(const void* p, long long i, int is64) {
    return is64 ? ((const long long*)p)[i] : (long long)((const int*)p)[i];
}

// ---------------- index dtype detection ----------------
__global__ void detect_kernel(const unsigned int* __restrict__ w) {
    __shared__ int any;
    if (threadIdx.x == 0) any = 0;
    __syncthreads();
    unsigned v = w[threadIdx.x * 2 + 1];
    if (v) atomicOr(&any, 1);
    __syncthreads();
    if (threadIdx.x == 0) g_is64 = any ? 0 : 1;
}

__global__ void zero_kernel() {
    int i = blockIdx.x * blockDim.x + threadIdx.x;
    if (i < N_NODES) g_deg_node[i] = 0;
    if (i < N_EDGES) g_deg_edge[i] = 0;
}

__global__ void count_kernel(const void* __restrict__ ei) {
    int i = blockIdx.x * blockDim.x + threadIdx.x;
    if (i >= NNZ) return;
    int is64 = g_is64;
    int r = (int)load_idx(ei, i, is64);
    int c = (int)load_idx(ei, (long long)NNZ + i, is64);
    atomicAdd(&g_deg_node[r], 1);
    atomicAdd(&g_deg_edge[c], 1);
}

// ---------------- parallel exclusive scan, 3 phases ----------------
__global__ void scan_part_kernel() {
    int which = blockIdx.y;
    const int* deg = which ? g_deg_edge : g_deg_node;
    int start = blockIdx.x * SCAN_CHUNK;
    int t = threadIdx.x;
    int base = start + t * 4;
    int sum = 0;
#pragma unroll
    for (int j = 0; j < 4; j++) {
        int i = base + j;
        if (i < N_NODES) sum += deg[i];
    }
    __shared__ int s[128];
    s[t] = sum;
    __syncthreads();
    for (int off = 64; off > 0; off >>= 1) {
        if (t < off) s[t] += s[t + off];
        __syncthreads();
    }
    if (t == 0) g_part[which][blockIdx.x] = s[0];
}

__global__ void scan_mid_kernel() {
    __shared__ int s[256];
    int t = threadIdx.x;
    int which = t >> 7;
    int j = t & 127;
    s[t] = (j < SCAN_NB) ? g_part[which][j] : 0;
    __syncthreads();
    for (int off = 1; off < 128; off <<= 1) {
        int v = (j >= off) ? s[t - off] : 0;
        __syncthreads();
        s[t] += v;
        __syncthreads();
    }
    if (j < SCAN_NB)
        g_part_ex[which][j] = (j > 0) ? s[t - 1] : 0;
    if (t == 0) { g_ptr_node[N_NODES] = NNZ; g_ptr_edge[N_EDGES] = NNZ; }
}

__global__ void scan_write_kernel() {
    int which = blockIdx.y;
    const int* deg = which ? g_deg_edge : g_deg_node;
    int* ptr = which ? g_ptr_edge : g_ptr_node;
    int* cur = which ? g_cur_edge : g_cur_node;
    float* inv = which ? g_binv : g_dinv;
    int start = blockIdx.x * SCAN_CHUNK;
    int t = threadIdx.x;
    int base = start + t * 4;
    int d[4];
    int sum = 0;
#pragma unroll
    for (int j = 0; j < 4; j++) {
        int i = base + j;
        d[j] = (i < N_NODES) ? deg[i] : 0;
        sum += d[j];
    }
    __shared__ int s[128];
    s[t] = sum;
    __syncthreads();
    for (int off = 1; off < 128; off <<= 1) {
        int v = (t >= off) ? s[t - off] : 0;
        __syncthreads();
        s[t] += v;
        __syncthreads();
    }
    int run = g_part_ex[which][blockIdx.x] + ((t > 0) ? s[t - 1] : 0);
#pragma unroll
    for (int j = 0; j < 4; j++) {
        int i = base + j;
        if (i < N_NODES) {
            ptr[i] = run;
            cur[i] = run;
            inv[i] = (d[j] > 0) ? 1.0f / (float)d[j] : 0.0f;
            run += d[j];
        }
    }
}

__global__ void fill_kernel(const void* __restrict__ ei) {
    int i = blockIdx.x * blockDim.x + threadIdx.x;
    if (i >= NNZ) return;
    int is64 = g_is64;
    int r = (int)load_idx(ei, i, is64);
    int c = (int)load_idx(ei, (long long)NNZ + i, is64);
    int p = atomicAdd(&g_cur_edge[c], 1);
    g_adj_edge[p] = r;
    int q = atomicAdd(&g_cur_node[r], 1);
    g_adj_node[q] = c;
}

__global__ void gstart_kernel(const void* __restrict__ batch) {
    int i = blockIdx.x * blockDim.x + threadIdx.x;
    if (i >= N_NODES) return;
    int is64 = g_is64;
    long long b  = load_idx(batch, i, is64);
    long long bp = (i == 0) ? -1 : load_idx(batch, i - 1, is64);
    if (b != bp)
        for (long long g = bp + 1; g <= b; g++) g_gstart[g] = i;
    if (i == N_NODES - 1)
        for (long long g = b + 1; g <= N_GRAPHS; g++) g_gstart[g] = N_NODES;
}

// ---------------- bf16x3 tensor-core GEMM ----------------
// C[M,256] = A[M,K] * B[K,256], fp32 in/out, error-compensated bf16 MMA:
//   A = Ahi + Alo, B = Bhi + Blo (bf16 splits)
//   C ~= Ahi*Bhi + Ahi*Blo + Alo*Bhi      (eps ~ 2^-16)
// block tile 128x128, BK=32, 8 warps, warp tile 64x32, mma.m16n8k16.bf16

#define A_STRIDE 40   // halves per A smem row (32 data + 8 pad) -> 80B, conflict-free ldmatrix
#define B_STRIDE 136  // halves per B smem row (128 data + 8 pad) -> 272B, conflict-free ldmatrix

__device__ __forceinline__ unsigned pack_bf16_hi(float v0, float v1, float& r0, float& r1) {
    __nv_bfloat16 h0 = __float2bfloat16(v0);
    __nv_bfloat16 h1 = __float2bfloat16(v1);
    r0 = v0 - __bfloat162float(h0);
    r1 = v1 - __bfloat162float(h1);
    __nv_bfloat162 p = {h0, h1};
    return *(unsigned*)&p;
}
__device__ __forceinline__ unsigned pack_bf16(float v0, float v1) {
    __nv_bfloat162 p = {__float2bfloat16(v0), __float2bfloat16(v1)};
    return *(unsigned*)&p;
}

__device__ __forceinline__ void ldmat4(unsigned* r, unsigned addr) {
    asm volatile("ldmatrix.sync.aligned.m8n8.x4.shared.b16 {%0,%1,%2,%3}, [%4];"
                 : "=r"(r[0]), "=r"(r[1]), "=r"(r[2]), "=r"(r[3]) : "r"(addr));
}
__device__ __forceinline__ void ldmat4t(unsigned* r, unsigned addr) {
    asm volatile("ldmatrix.sync.aligned.m8n8.x4.trans.shared.b16 {%0,%1,%2,%3}, [%4];"
                 : "=r"(r[0]), "=r"(r[1]), "=r"(r[2]), "=r"(r[3]) : "r"(addr));
}
__device__ __forceinline__ void mma16816(float* c, const unsigned* a, const unsigned* b) {
    asm volatile("mma.sync.aligned.m16n8k16.row.col.f32.bf16.bf16.f32 "
                 "{%0,%1,%2,%3}, {%4,%5,%6,%7}, {%8,%9}, {%0,%1,%2,%3};"
                 : "+f"(c[0]), "+f"(c[1]), "+f"(c[2]), "+f"(c[3])
                 : "r"(a[0]), "r"(a[1]), "r"(a[2]), "r"(a[3]), "r"(b[0]), "r"(b[1]));
}

__global__ __launch_bounds__(256, 1) void mma_gemm_kernel(
    const float* __restrict__ A, const float* __restrict__ B,
    float* __restrict__ C, int M, int K) {
    __shared__ unsigned Ahi[128 * A_STRIDE / 2];
    __shared__ unsigned Alo[128 * A_STRIDE / 2];
    __shared__ unsigned Bhi[32 * B_STRIDE / 2];
    __shared__ unsigned Blo[32 * B_STRIDE / 2];

    int t = threadIdx.x;
    int lane = t & 31;
    int warpid = t >> 5;
    int warp_m = (warpid & 1) * 64;
    int warp_n = (warpid >> 1) * 32;
    int bx = blockIdx.x, by = blockIdx.y;

    float acc[4][4][4];
#pragma unroll
    for (int i = 0; i < 4; i++)
#pragma unroll
        for (int j = 0; j < 4; j++)
#pragma unroll
            for (int k = 0; k < 4; k++) acc[i][j][k] = 0.f;

    // ldmatrix lane geometry
    int tt = lane >> 3, rr = lane & 7;
    unsigned a_hi_base = (unsigned)__cvta_generic_to_shared(Ahi);
    unsigned a_lo_base = (unsigned)__cvta_generic_to_shared(Alo);
    unsigned b_hi_base = (unsigned)__cvta_generic_to_shared(Bhi);
    unsigned b_lo_base = (unsigned)__cvta_generic_to_shared(Blo);

    for (int k0 = 0; k0 < K; k0 += 32) {
        // ---- stage A tile 128x32 (convert fp32 -> bf16 hi/lo) ----
#pragma unroll
        for (int p = 0; p < 4; p++) {
            int f4_id = t + p * 256;            // 0..1023
            int row = f4_id >> 3;               // 0..127
            int f4 = f4_id & 7;                 // 0..7
            int grow = by * 128 + row;
            float4 v;
            if (grow < M) v = *(const float4*)(A + (size_t)grow * K + k0 + f4 * 4);
            else          v = make_float4(0.f, 0.f, 0.f, 0.f);
            float r0, r1, r2, r3;
            unsigned h01 = pack_bf16_hi(v.x, v.y, r0, r1);
            unsigned h23 = pack_bf16_hi(v.z, v.w, r2, r3);
            int base = row * (A_STRIDE / 2) + f4 * 2;
            Ahi[base]     = h01;
            Ahi[base + 1] = h23;
            Alo[base]     = pack_bf16(r0, r1);
            Alo[base + 1] = pack_bf16(r2, r3);
        }
        // ---- stage B tile 32x128 ----
#pragma unroll
        for (int p = 0; p < 4; p++) {
            int f4_id = t + p * 256;            // 0..1023
            int row = f4_id >> 5;               // 0..31
            int f4c = f4_id & 31;               // 0..31
            float4 v = *(const float4*)(B + (size_t)(k0 + row) * 256 + bx * 128 + f4c * 4);
            float r0, r1, r2, r3;
            unsigned h01 = pack_bf16_hi(v.x, v.y, r0, r1);
            unsigned h23 = pack_bf16_hi(v.z, v.w, r2, r3);
            int base = row * (B_STRIDE / 2) + f4c * 2;
            Bhi[base]     = h01;
            Bhi[base + 1] = h23;
            Blo[base]     = pack_bf16(r0, r1);
            Blo[base + 1] = pack_bf16(r2, r3);
        }
        __syncthreads();

        // ---- compute 2 x k16 steps ----
#pragma unroll
        for (int ks = 0; ks < 2; ks++) {
            int k16 = ks * 16;
            unsigned ahi[4][4], alo[4][4];
#pragma unroll
            for (int mf = 0; mf < 4; mf++) {
                int row = warp_m + mf * 16 + (tt & 1) * 8 + rr;
                int kk = k16 + (tt >> 1) * 8;
                unsigned off = (unsigned)(row * A_STRIDE + kk) * 2;
                ldmat4(ahi[mf], a_hi_base + off);
                ldmat4(alo[mf], a_lo_base + off);
            }
            unsigned bhi[4][2], blo[4][2];
#pragma unroll
            for (int nf2 = 0; nf2 < 2; nf2++) {
                int row = k16 + (tt & 1) * 8 + rr;
                int col = warp_n + nf2 * 16 + (tt >> 1) * 8;
                unsigned off = (unsigned)(row * B_STRIDE + col) * 2;
                unsigned rh[4], rl[4];
                ldmat4t(rh, b_hi_base + off);
                ldmat4t(rl, b_lo_base + off);
                bhi[nf2 * 2][0] = rh[0]; bhi[nf2 * 2][1] = rh[1];
                bhi[nf2 * 2 + 1][0] = rh[2]; bhi[nf2 * 2 + 1][1] = rh[3];
                blo[nf2 * 2][0] = rl[0]; blo[nf2 * 2][1] = rl[1];
                blo[nf2 * 2 + 1][0] = rl[2]; blo[nf2 * 2 + 1][1] = rl[3];
            }
#pragma unroll
            for (int mf = 0; mf < 4; mf++)
#pragma unroll
                for (int nf = 0; nf < 4; nf++) {
                    mma16816(acc[mf][nf], ahi[mf], bhi[nf]);
                    mma16816(acc[mf][nf], ahi[mf], blo[nf]);
                    mma16816(acc[mf][nf], alo[mf], bhi[nf]);
                }
        }
        __syncthreads();
    }

    // ---- epilogue ----
    int g = lane >> 2, tg = lane & 3;
#pragma unroll
    for (int mf = 0; mf < 4; mf++) {
#pragma unroll
        for (int nf = 0; nf < 4; nf++) {
            int col = bx * 128 + warp_n + nf * 8 + tg * 2;
            int row0 = by * 128 + warp_m + mf * 16 + g;
            int row1 = row0 + 8;
            if (row0 < M)
                *(float2*)(C + (size_t)row0 * 256 + col) = make_float2(acc[mf][nf][0], acc[mf][nf][1]);
            if (row1 < M)
                *(float2*)(C + (size_t)row1 * 256 + col) = make_float2(acc[mf][nf][2], acc[mf][nf][3]);
        }
    }
}

// ---------------- gathers (CSR, no atomics), 1 warp per segment ----------------
__global__ __launch_bounds__(256) void gather_edge_kernel() {
    int seg = blockIdx.x * 8 + threadIdx.y;
    int t = threadIdx.x;
    __shared__ int idx[8][32];
    int s = g_ptr_edge[seg], en = g_ptr_edge[seg + 1];
    float4 a0 = make_float4(0,0,0,0), a1 = make_float4(0,0,0,0);
    for (int base = s; base < en; base += 32) {
        int cnt = min(32, en - base);
        if (t < cnt) idx[threadIdx.y][t] = g_adj_edge[base + t];
        __syncwarp();
#pragma unroll 2
        for (int j = 0; j < cnt; j++) {
            const float* row = g_xw + (size_t)idx[threadIdx.y][j] * HID;
            float4 v0 = *(const float4*)(row + 4 * t);
            float4 v1 = *(const float4*)(row + 128 + 4 * t);
            a0.x += v0.x; a0.y += v0.y; a0.z += v0.z; a0.w += v0.w;
            a1.x += v1.x; a1.y += v1.y; a1.z += v1.z; a1.w += v1.w;
        }
        __syncwarp();
    }
    float b = g_binv[seg];
    float* o = g_e + (size_t)seg * HID;
    *(float4*)(o + 4 * t)       = make_float4(a0.x*b, a0.y*b, a0.z*b, a0.w*b);
    *(float4*)(o + 128 + 4 * t) = make_float4(a1.x*b, a1.y*b, a1.z*b, a1.w*b);
}

__global__ __launch_bounds__(256) void gather_node_kernel(const float* __restrict__ bias) {
    int seg = blockIdx.x * 8 + threadIdx.y;
    int t = threadIdx.x;
    __shared__ int idx[8][32];
    int s = g_ptr_node[seg], en = g_ptr_node[seg + 1];
    float4 a0 = make_float4(0,0,0,0), a1 = make_float4(0,0,0,0);
    for (int base = s; base < en; base += 32) {
        int cnt = min(32, en - base);
        if (t < cnt) idx[threadIdx.y][t] = g_adj_node[base + t];
        __syncwarp();
#pragma unroll 2
        for (int j = 0; j < cnt; j++) {
            const float* row = g_e + (size_t)idx[threadIdx.y][j] * HID;
            float4 v0 = *(const float4*)(row + 4 * t);
            float4 v1 = *(const float4*)(row + 128 + 4 * t);
            a0.x += v0.x; a0.y += v0.y; a0.z += v0.z; a0.w += v0.w;
            a1.x += v1.x; a1.y += v1.y; a1.z += v1.z; a1.w += v1.w;
        }
        __syncwarp();
    }
    float d = g_dinv[seg];
    float4 c0 = *(const float4*)(bias + 4 * t);
    float4 c1 = *(const float4*)(bias + 128 + 4 * t);
    float* o = g_h + (size_t)seg * HID;
    *(float4*)(o + 4 * t) = make_float4(
        fmaxf(a0.x*d + c0.x, 0.f), fmaxf(a0.y*d + c0.y, 0.f),
        fmaxf(a0.z*d + c0.z, 0.f), fmaxf(a0.w*d + c0.w, 0.f));
    *(float4*)(o + 128 + 4 * t) = make_float4(
        fmaxf(a1.x*d + c1.x, 0.f), fmaxf(a1.y*d + c1.y, 0.f),
        fmaxf(a1.z*d + c1.z, 0.f), fmaxf(a1.w*d + c1.w, 0.f));
}

__global__ __launch_bounds__(256) void pool_kernel() {
    int g = blockIdx.x, t = threadIdx.x;
    int s = g_gstart[g], e = g_gstart[g + 1];
    float acc = 0.f;
    for (int i = s; i < e; i++) acc += g_h[(size_t)i * HID + t];
    int c = e - s;
    float inv = 1.0f / (float)max(c, 1);
    g_pooled[g * HID + t] = acc * inv;
}

__global__ __launch_bounds__(256) void mlp_kernel(
    const float* __restrict__ M1, const float* __restrict__ bM1,
    const float* __restrict__ M2, const float* __restrict__ bM2,
    float* __restrict__ out) {
    int g = blockIdx.x, t = threadIdx.x;
    __shared__ float p[HID];
    __shared__ float z[HID];
    __shared__ float red[HID];
    p[t] = g_pooled[g * HID + t];
    __syncthreads();
    float acc = bM1[t];
#pragma unroll 8
    for (int k = 0; k < HID; k++) acc += p[k] * M1[k * HID + t];
    z[t] = fmaxf(acc, 0.f);
    __syncthreads();
    for (int o = 0; o < OUT_C; o++) {
        red[t] = z[t] * M2[t * OUT_C + o];
        __syncthreads();
        for (int s = 128; s > 0; s >>= 1) {
            if (t < s) red[t] += red[t + s];
            __syncthreads();
        }
        if (t == 0) out[g * OUT_C + o] = red[0] + bM2[o];
        __syncthreads();
    }
}

// ---------------- launch ----------------
extern "C" void kernel_launch(void* const* d_in, const int* in_sizes, int n_in,
                              void* d_out, int out_size) {
    const float* x    = (const float*)d_in[0];
    const void*  ei   = d_in[1];
    const void*  batch= d_in[2];
    const float* W0   = (const float*)d_in[3];
    const float* b0   = (const float*)d_in[4];
    const float* W1   = (const float*)d_in[5];
    const float* b1   = (const float*)d_in[6];
    const float* W2   = (const float*)d_in[7];
    const float* b2   = (const float*)d_in[8];
    const float* M1   = (const float*)d_in[9];
    const float* bM1  = (const float*)d_in[10];
    const float* M2   = (const float*)d_in[11];
    const float* bM2  = (const float*)d_in[12];
    float* out = (float*)d_out;

    float* hptr  = nullptr;
    float* xwptr = nullptr;
    cudaGetSymbolAddress((void**)&hptr,  g_h);
    cudaGetSymbolAddress((void**)&xwptr, g_xw);

    detect_kernel<<<1, 256>>>((const unsigned int*)ei);
    zero_kernel<<<(N_NODES + 255) / 256, 256>>>();
    count_kernel<<<(NNZ + 255) / 256, 256>>>(ei);
    scan_part_kernel<<<dim3(SCAN_NB, 2), 128>>>();
    scan_mid_kernel<<<1, 256>>>();
    scan_write_kernel<<<dim3(SCAN_NB, 2), 128>>>();
    fill_kernel<<<(NNZ + 255) / 256, 256>>>(ei);
    gstart_kernel<<<(N_NODES + 255) / 256, 256>>>(batch);

    const float* Ws[3] = {W0, W1, W2};
    const float* bs[3] = {b0, b1, b2};
    const float* A = x;
    int K = IN_C;
    dim3 ggrid(2, (N_NODES + 127) / 128);
    dim3 gb(32, 8);
    for (int l = 0; l < 3; l++) {
        mma_gemm_kernel<<<ggrid, 256>>>(A, Ws[l], xwptr, N_NODES, K);
        gather_edge_kernel<<<N_EDGES / 8, gb>>>();
        gather_node_kernel<<<N_NODES / 8, gb>>>(bs[l]);
        A = hptr;
        K = HID;
    }
    pool_kernel<<<N_GRAPHS, 256>>>();
    mlp_kernel<<<N_GRAPHS, 256>>>(M1, bM1, M2, bM2, out);
}

// round 6
// speedup vs baseline: 2.7236x; 1.1857x over previous
#include <cuda_runtime.h>
#include <cuda_bf16.h>
#include <cuda_fp16.h>

#define N_NODES  50000
#define N_EDGES  50000
#define NNZ      500000
#define N_GRAPHS 50
#define IN_C     128
#define HID      256
#define OUT_C    2

#define SCAN_CHUNK 512
#define SCAN_NB    98    // 98*512 = 50176 >= 50000

// ---------------- device scratch (static, allocation-free) ----------------
__device__ int   g_is64;
__device__ int   g_deg_node[N_NODES];
__device__ int   g_deg_edge[N_EDGES];
__device__ int   g_ptr_node[N_NODES + 1];
__device__ int   g_ptr_edge[N_EDGES + 1];
__device__ int   g_cur_node[N_NODES];
__device__ int   g_cur_edge[N_EDGES];
__device__ int   g_adj_node[NNZ];
__device__ int   g_adj_edge[NNZ];
__device__ float g_dinv[N_NODES];
__device__ float g_binv[N_EDGES];
__device__ int   g_gstart[N_GRAPHS + 1];
__device__ int   g_part[2][SCAN_NB];
__device__ int   g_part_ex[2][SCAN_NB];
__device__ __half g_xw_h[(size_t)N_NODES * HID];   // GEMM output, fp16
__device__ __half g_e_h [(size_t)N_EDGES * HID];   // edge feats, fp16
__device__ float  g_h   [(size_t)N_NODES * HID];   // node feats, fp32
__device__ float  g_pooled[N_GRAPHS * HID];

__device__ __forceinline__ long long load_idx(const void* p, long long i, int is64) {
    return is64 ? ((const long long*)p)[i] : (long long)((const int*)p)[i];
}

// ---------------- index dtype detection (2048 samples) ----------------
__global__ void detect_kernel(const unsigned int* __restrict__ w) {
    __shared__ int any;
    if (threadIdx.x == 0) any = 0;
    __syncthreads();
    int nz = 0;
#pragma unroll
    for (int p = 0; p < 8; p++) {
        unsigned v = w[(threadIdx.x + p * 256) * 2 + 1];
        nz |= (v != 0);
    }
    if (nz) atomicOr(&any, 1);
    __syncthreads();
    if (threadIdx.x == 0) g_is64 = any ? 0 : 1;
}

__global__ void zero_kernel() {
    int i = blockIdx.x * blockDim.x + threadIdx.x;
    if (i < N_NODES) g_deg_node[i] = 0;
    if (i < N_EDGES) g_deg_edge[i] = 0;
}

__global__ void count_kernel(const void* __restrict__ ei) {
    int i = blockIdx.x * blockDim.x + threadIdx.x;
    if (i >= NNZ) return;
    int is64 = g_is64;
    int r = (int)load_idx(ei, i, is64);
    int c = (int)load_idx(ei, (long long)NNZ + i, is64);
    // clamp defensively: even corrupt data must not scribble outside arrays
    r = min(max(r, 0), N_NODES - 1);
    c = min(max(c, 0), N_EDGES - 1);
    atomicAdd(&g_deg_node[r], 1);
    atomicAdd(&g_deg_edge[c], 1);
}

// ---------------- parallel exclusive scan, 3 phases ----------------
__global__ void scan_part_kernel() {
    int which = blockIdx.y;
    const int* deg = which ? g_deg_edge : g_deg_node;
    int start = blockIdx.x * SCAN_CHUNK;
    int t = threadIdx.x;
    int base = start + t * 4;
    int sum = 0;
#pragma unroll
    for (int j = 0; j < 4; j++) {
        int i = base + j;
        if (i < N_NODES) sum += deg[i];
    }
    __shared__ int s[128];
    s[t] = sum;
    __syncthreads();
    for (int off = 64; off > 0; off >>= 1) {
        if (t < off) s[t] += s[t + off];
        __syncthreads();
    }
    if (t == 0) g_part[which][blockIdx.x] = s[0];
}

__global__ void scan_mid_kernel() {
    __shared__ int s[256];
    int t = threadIdx.x;
    int which = t >> 7;
    int j = t & 127;
    s[t] = (j < SCAN_NB) ? g_part[which][j] : 0;
    __syncthreads();
    for (int off = 1; off < 128; off <<= 1) {
        int v = (j >= off) ? s[t - off] : 0;
        __syncthreads();
        s[t] += v;
        __syncthreads();
    }
    if (j < SCAN_NB)
        g_part_ex[which][j] = (j > 0) ? s[t - 1] : 0;
    if (t == 0) { g_ptr_node[N_NODES] = NNZ; g_ptr_edge[N_EDGES] = NNZ; }
}

__global__ void scan_write_kernel() {
    int which = blockIdx.y;
    const int* deg = which ? g_deg_edge : g_deg_node;
    int* ptr = which ? g_ptr_edge : g_ptr_node;
    int* cur = which ? g_cur_edge : g_cur_node;
    float* inv = which ? g_binv : g_dinv;
    int start = blockIdx.x * SCAN_CHUNK;
    int t = threadIdx.x;
    int base = start + t * 4;
    int d[4];
    int sum = 0;
#pragma unroll
    for (int j = 0; j < 4; j++) {
        int i = base + j;
        d[j] = (i < N_NODES) ? deg[i] : 0;
        sum += d[j];
    }
    __shared__ int s[128];
    s[t] = sum;
    __syncthreads();
    for (int off = 1; off < 128; off <<= 1) {
        int v = (t >= off) ? s[t - off] : 0;
        __syncthreads();
        s[t] += v;
        __syncthreads();
    }
    int run = g_part_ex[which][blockIdx.x] + ((t > 0) ? s[t - 1] : 0);
#pragma unroll
    for (int j = 0; j < 4; j++) {
        int i = base + j;
        if (i < N_NODES) {
            ptr[i] = run;
            cur[i] = run;
            inv[i] = (d[j] > 0) ? 1.0f / (float)d[j] : 0.0f;
            run += d[j];
        }
    }
}

__global__ void fill_kernel(const void* __restrict__ ei) {
    int i = blockIdx.x * blockDim.x + threadIdx.x;
    if (i >= NNZ) return;
    int is64 = g_is64;
    int r = (int)load_idx(ei, i, is64);
    int c = (int)load_idx(ei, (long long)NNZ + i, is64);
    r = min(max(r, 0), N_NODES - 1);
    c = min(max(c, 0), N_EDGES - 1);
    int p = atomicAdd(&g_cur_edge[c], 1);
    if (p >= 0 && p < NNZ) g_adj_edge[p] = r;
    int q = atomicAdd(&g_cur_node[r], 1);
    if (q >= 0 && q < NNZ) g_adj_node[q] = c;
}

__global__ void gstart_kernel(const void* __restrict__ batch) {
    int i = blockIdx.x * blockDim.x + threadIdx.x;
    if (i >= N_NODES) return;
    int is64 = g_is64;
    long long b  = load_idx(batch, i, is64);
    long long bp = (i == 0) ? -1 : load_idx(batch, i - 1, is64);
    if (b  < 0) b  = 0;  if (b  > N_GRAPHS - 1) b  = N_GRAPHS - 1;
    if (bp < -1) bp = -1; if (bp > N_GRAPHS - 1) bp = N_GRAPHS - 1;
    if (b != bp)
        for (long long g = bp + 1; g <= b; g++) g_gstart[g] = i;
    if (i == N_NODES - 1)
        for (long long g = b + 1; g <= N_GRAPHS; g++) g_gstart[g] = N_NODES;
}

// ---------------- bf16x3 tensor-core GEMM ----------------
// C[M,256] (fp16 out) = A[M,K] (fp32) * B[K,256] (fp32), error-compensated bf16 MMA.

#define A_STRIDE 40   // halves per A smem row (32 data + 8 pad)
#define B_STRIDE 136  // halves per B smem row (128 data + 8 pad)

__device__ __forceinline__ unsigned pack_bf16_hi(float v0, float v1, float& r0, float& r1) {
    __nv_bfloat16 h0 = __float2bfloat16(v0);
    __nv_bfloat16 h1 = __float2bfloat16(v1);
    r0 = v0 - __bfloat162float(h0);
    r1 = v1 - __bfloat162float(h1);
    __nv_bfloat162 p = {h0, h1};
    return *(unsigned*)&p;
}
__device__ __forceinline__ unsigned pack_bf16(float v0, float v1) {
    __nv_bfloat162 p = {__float2bfloat16(v0), __float2bfloat16(v1)};
    return *(unsigned*)&p;
}

__device__ __forceinline__ void ldmat4(unsigned* r, unsigned addr) {
    asm volatile("ldmatrix.sync.aligned.m8n8.x4.shared.b16 {%0,%1,%2,%3}, [%4];"
                 : "=r"(r[0]), "=r"(r[1]), "=r"(r[2]), "=r"(r[3]) : "r"(addr));
}
__device__ __forceinline__ void ldmat4t(unsigned* r, unsigned addr) {
    asm volatile("ldmatrix.sync.aligned.m8n8.x4.trans.shared.b16 {%0,%1,%2,%3}, [%4];"
                 : "=r"(r[0]), "=r"(r[1]), "=r"(r[2]), "=r"(r[3]) : "r"(addr));
}
__device__ __forceinline__ void mma16816(float* c, const unsigned* a, const unsigned* b) {
    asm volatile("mma.sync.aligned.m16n8k16.row.col.f32.bf16.bf16.f32 "
                 "{%0,%1,%2,%3}, {%4,%5,%6,%7}, {%8,%9}, {%0,%1,%2,%3};"
                 : "+f"(c[0]), "+f"(c[1]), "+f"(c[2]), "+f"(c[3])
                 : "r"(a[0]), "r"(a[1]), "r"(a[2]), "r"(a[3]), "r"(b[0]), "r"(b[1]));
}

__global__ __launch_bounds__(256, 1) void mma_gemm_kernel(
    const float* __restrict__ A, const float* __restrict__ B,
    __half* __restrict__ C, int M, int K) {
    __shared__ unsigned Ahi[128 * A_STRIDE / 2];
    __shared__ unsigned Alo[128 * A_STRIDE / 2];
    __shared__ unsigned Bhi[32 * B_STRIDE / 2];
    __shared__ unsigned Blo[32 * B_STRIDE / 2];

    int t = threadIdx.x;
    int lane = t & 31;
    int warpid = t >> 5;
    int warp_m = (warpid & 1) * 64;
    int warp_n = (warpid >> 1) * 32;
    int bx = blockIdx.x, by = blockIdx.y;

    float acc[4][4][4];
#pragma unroll
    for (int i = 0; i < 4; i++)
#pragma unroll
        for (int j = 0; j < 4; j++)
#pragma unroll
            for (int k = 0; k < 4; k++) acc[i][j][k] = 0.f;

    int tt = lane >> 3, rr = lane & 7;
    unsigned a_hi_base = (unsigned)__cvta_generic_to_shared(Ahi);
    unsigned a_lo_base = (unsigned)__cvta_generic_to_shared(Alo);
    unsigned b_hi_base = (unsigned)__cvta_generic_to_shared(Bhi);
    unsigned b_lo_base = (unsigned)__cvta_generic_to_shared(Blo);

    for (int k0 = 0; k0 < K; k0 += 32) {
#pragma unroll
        for (int p = 0; p < 4; p++) {
            int f4_id = t + p * 256;
            int row = f4_id >> 3;
            int f4 = f4_id & 7;
            int grow = by * 128 + row;
            float4 v;
            if (grow < M) v = *(const float4*)(A + (size_t)grow * K + k0 + f4 * 4);
            else          v = make_float4(0.f, 0.f, 0.f, 0.f);
            float r0, r1, r2, r3;
            unsigned h01 = pack_bf16_hi(v.x, v.y, r0, r1);
            unsigned h23 = pack_bf16_hi(v.z, v.w, r2, r3);
            int base = row * (A_STRIDE / 2) + f4 * 2;
            Ahi[base]     = h01;
            Ahi[base + 1] = h23;
            Alo[base]     = pack_bf16(r0, r1);
            Alo[base + 1] = pack_bf16(r2, r3);
        }
#pragma unroll
        for (int p = 0; p < 4; p++) {
            int f4_id = t + p * 256;
            int row = f4_id >> 5;
            int f4c = f4_id & 31;
            float4 v = *(const float4*)(B + (size_t)(k0 + row) * 256 + bx * 128 + f4c * 4);
            float r0, r1, r2, r3;
            unsigned h01 = pack_bf16_hi(v.x, v.y, r0, r1);
            unsigned h23 = pack_bf16_hi(v.z, v.w, r2, r3);
            int base = row * (B_STRIDE / 2) + f4c * 2;
            Bhi[base]     = h01;
            Bhi[base + 1] = h23;
            Blo[base]     = pack_bf16(r0, r1);
            Blo[base + 1] = pack_bf16(r2, r3);
        }
        __syncthreads();

#pragma unroll
        for (int ks = 0; ks < 2; ks++) {
            int k16 = ks * 16;
            unsigned ahi[4][4], alo[4][4];
#pragma unroll
            for (int mf = 0; mf < 4; mf++) {
                int row = warp_m + mf * 16 + (tt & 1) * 8 + rr;
                int kk = k16 + (tt >> 1) * 8;
                unsigned off = (unsigned)(row * A_STRIDE + kk) * 2;
                ldmat4(ahi[mf], a_hi_base + off);
                ldmat4(alo[mf], a_lo_base + off);
            }
            unsigned bhi[4][2], blo[4][2];
#pragma unroll
            for (int nf2 = 0; nf2 < 2; nf2++) {
                int row = k16 + (tt & 1) * 8 + rr;
                int col = warp_n + nf2 * 16 + (tt >> 1) * 8;
                unsigned off = (unsigned)(row * B_STRIDE + col) * 2;
                unsigned rh[4], rl[4];
                ldmat4t(rh, b_hi_base + off);
                ldmat4t(rl, b_lo_base + off);
                bhi[nf2 * 2][0] = rh[0]; bhi[nf2 * 2][1] = rh[1];
                bhi[nf2 * 2 + 1][0] = rh[2]; bhi[nf2 * 2 + 1][1] = rh[3];
                blo[nf2 * 2][0] = rl[0]; blo[nf2 * 2][1] = rl[1];
                blo[nf2 * 2 + 1][0] = rl[2]; blo[nf2 * 2 + 1][1] = rl[3];
            }
#pragma unroll
            for (int mf = 0; mf < 4; mf++)
#pragma unroll
                for (int nf = 0; nf < 4; nf++) {
                    mma16816(acc[mf][nf], ahi[mf], bhi[nf]);
                    mma16816(acc[mf][nf], ahi[mf], blo[nf]);
                    mma16816(acc[mf][nf], alo[mf], bhi[nf]);
                }
        }
        __syncthreads();
    }

    // epilogue: convert fp32 acc -> fp16 output
    int g = lane >> 2, tg = lane & 3;
#pragma unroll
    for (int mf = 0; mf < 4; mf++) {
#pragma unroll
        for (int nf = 0; nf < 4; nf++) {
            int col = bx * 128 + warp_n + nf * 8 + tg * 2;
            int row0 = by * 128 + warp_m + mf * 16 + g;
            int row1 = row0 + 8;
            if (row0 < M)
                *(__half2*)(C + (size_t)row0 * 256 + col) = __floats2half2_rn(acc[mf][nf][0], acc[mf][nf][1]);
            if (row1 < M)
                *(__half2*)(C + (size_t)row1 * 256 + col) = __floats2half2_rn(acc[mf][nf][2], acc[mf][nf][3]);
        }
    }
}

// ---------------- gathers (CSR, no atomics), 1 warp per segment, fp16 rows ----------------
__global__ __launch_bounds__(256) void gather_edge_kernel() {
    int seg = blockIdx.x * 8 + threadIdx.y;
    int t = threadIdx.x;
    __shared__ int idx[8][32];
    int s = g_ptr_edge[seg], en = g_ptr_edge[seg + 1];
    // defensive clamp: loop must terminate under any data
    s = min(max(s, 0), NNZ); en = min(max(en, s), NNZ);
    float2 a0 = make_float2(0,0), a1 = make_float2(0,0), a2 = make_float2(0,0), a3 = make_float2(0,0);
    for (int base = s; base < en; base += 32) {
        int cnt = min(32, en - base);
        if (t < cnt) idx[threadIdx.y][t] = g_adj_edge[base + t];
        __syncwarp();
        for (int j = 0; j < cnt; j++) {
            const uint4* row = (const uint4*)(g_xw_h + (size_t)idx[threadIdx.y][j] * HID);
            uint4 v = row[t];
            float2 f0 = __half22float2(*(__half2*)&v.x);
            float2 f1 = __half22float2(*(__half2*)&v.y);
            float2 f2 = __half22float2(*(__half2*)&v.z);
            float2 f3 = __half22float2(*(__half2*)&v.w);
            a0.x += f0.x; a0.y += f0.y; a1.x += f1.x; a1.y += f1.y;
            a2.x += f2.x; a2.y += f2.y; a3.x += f3.x; a3.y += f3.y;
        }
        __syncwarp();
    }
    float b = g_binv[seg];
    uint4 ov;
    *(__half2*)&ov.x = __floats2half2_rn(a0.x * b, a0.y * b);
    *(__half2*)&ov.y = __floats2half2_rn(a1.x * b, a1.y * b);
    *(__half2*)&ov.z = __floats2half2_rn(a2.x * b, a2.y * b);
    *(__half2*)&ov.w = __floats2half2_rn(a3.x * b, a3.y * b);
    ((uint4*)(g_e_h + (size_t)seg * HID))[t] = ov;
}

__global__ __launch_bounds__(256) void gather_node_kernel(const float* __restrict__ bias) {
    int seg = blockIdx.x * 8 + threadIdx.y;
    int t = threadIdx.x;
    __shared__ int idx[8][32];
    int s = g_ptr_node[seg], en = g_ptr_node[seg + 1];
    s = min(max(s, 0), NNZ); en = min(max(en, s), NNZ);
    float2 a0 = make_float2(0,0), a1 = make_float2(0,0), a2 = make_float2(0,0), a3 = make_float2(0,0);
    for (int base = s; base < en; base += 32) {
        int cnt = min(32, en - base);
        if (t < cnt) idx[threadIdx.y][t] = g_adj_node[base + t];
        __syncwarp();
        for (int j = 0; j < cnt; j++) {
            const uint4* row = (const uint4*)(g_e_h + (size_t)idx[threadIdx.y][j] * HID);
            uint4 v = row[t];
            float2 f0 = __half22float2(*(__half2*)&v.x);
            float2 f1 = __half22float2(*(__half2*)&v.y);
            float2 f2 = __half22float2(*(__half2*)&v.z);
            float2 f3 = __half22float2(*(__half2*)&v.w);
            a0.x += f0.x; a0.y += f0.y; a1.x += f1.x; a1.y += f1.y;
            a2.x += f2.x; a2.y += f2.y; a3.x += f3.x; a3.y += f3.y;
        }
        __syncwarp();
    }
    float d = g_dinv[seg];
    const float4* bz = (const float4*)(bias + 8 * t);
    float4 c0 = bz[0], c1 = bz[1];
    float* o = g_h + (size_t)seg * HID + 8 * t;
    *(float4*)(o) = make_float4(
        fmaxf(a0.x * d + c0.x, 0.f), fmaxf(a0.y * d + c0.y, 0.f),
        fmaxf(a1.x * d + c0.z, 0.f), fmaxf(a1.y * d + c0.w, 0.f));
    *(float4*)(o + 4) = make_float4(
        fmaxf(a2.x * d + c1.x, 0.f), fmaxf(a2.y * d + c1.y, 0.f),
        fmaxf(a3.x * d + c1.z, 0.f), fmaxf(a3.y * d + c1.w, 0.f));
}

__global__ __launch_bounds__(256) void pool_kernel() {
    int g = blockIdx.x, t = threadIdx.x;
    int s = g_gstart[g], e = g_gstart[g + 1];
    s = min(max(s, 0), N_NODES); e = min(max(e, s), N_NODES);
    float acc = 0.f;
    for (int i = s; i < e; i++) acc += g_h[(size_t)i * HID + t];
    int c = e - s;
    float inv = 1.0f / (float)max(c, 1);
    g_pooled[g * HID + t] = acc * inv;
}

__global__ __launch_bounds__(256) void mlp_kernel(
    const float* __restrict__ M1, const float* __restrict__ bM1,
    const float* __restrict__ M2, const float* __restrict__ bM2,
    float* __restrict__ out) {
    int g = blockIdx.x, t = threadIdx.x;
    __shared__ float p[HID];
    __shared__ float z[HID];
    __shared__ float red[HID];
    p[t] = g_pooled[g * HID + t];
    __syncthreads();
    float acc = bM1[t];
#pragma unroll 8
    for (int k = 0; k < HID; k++) acc += p[k] * M1[k * HID + t];
    z[t] = fmaxf(acc, 0.f);
    __syncthreads();
    for (int o = 0; o < OUT_C; o++) {
        red[t] = z[t] * M2[t * OUT_C + o];
        __syncthreads();
        for (int s = 128; s > 0; s >>= 1) {
            if (t < s) red[t] += red[t + s];
            __syncthreads();
        }
        if (t == 0) out[g * OUT_C + o] = red[0] + bM2[o];
        __syncthreads();
    }
}

// ---------------- launch ----------------
extern "C" void kernel_launch(void* const* d_in, const int* in_sizes, int n_in,
                              void* d_out, int out_size) {
    const float* x    = (const float*)d_in[0];
    const void*  ei   = d_in[1];
    const void*  batch= d_in[2];
    const float* W0   = (const float*)d_in[3];
    const float* b0   = (const float*)d_in[4];
    const float* W1   = (const float*)d_in[5];
    const float* b1   = (const float*)d_in[6];
    const float* W2   = (const float*)d_in[7];
    const float* b2   = (const float*)d_in[8];
    const float* M1   = (const float*)d_in[9];
    const float* bM1  = (const float*)d_in[10];
    const float* M2   = (const float*)d_in[11];
    const float* bM2  = (const float*)d_in[12];
    float* out = (float*)d_out;

    float*  hptr  = nullptr;
    __half* xwptr = nullptr;
    cudaGetSymbolAddress((void**)&hptr,  g_h);
    cudaGetSymbolAddress((void**)&xwptr, g_xw_h);

    detect_kernel<<<1, 256>>>((const unsigned int*)ei);
    zero_kernel<<<(N_NODES + 255) / 256, 256>>>();
    count_kernel<<<(NNZ + 255) / 256, 256>>>(ei);
    scan_part_kernel<<<dim3(SCAN_NB, 2), 128>>>();
    scan_mid_kernel<<<1, 256>>>();
    scan_write_kernel<<<dim3(SCAN_NB, 2), 128>>>();
    fill_kernel<<<(NNZ + 255) / 256, 256>>>(ei);
    gstart_kernel<<<(N_NODES + 255) / 256, 256>>>(batch);

    const float* Ws[3] = {W0, W1, W2};
    const float* bs[3] = {b0, b1, b2};
    const float* A = x;
    int K = IN_C;
    dim3 ggrid(2, (N_NODES + 127) / 128);
    dim3 gb(32, 8);
    for (int l = 0; l < 3; l++) {
        mma_gemm_kernel<<<ggrid, 256>>>(A, Ws[l], xwptr, N_NODES, K);
        gather_edge_kernel<<<N_EDGES / 8, gb>>>();
        gather_node_kernel<<<N_NODES / 8, gb>>>(bs[l]);
        A = hptr;
        K = HID;
    }
    pool_kernel<<<N_GRAPHS, 256>>>();
    mlp_kernel<<<N_GRAPHS, 256>>>(M1, bM1, M2, bM2, out);
}

// round 10
// speedup vs baseline: 3.6199x; 1.3291x over previous
#include <cuda_runtime.h>
#include <cuda_bf16.h>
#include <cuda_fp16.h>

#define N_NODES  50000
#define N_EDGES  50000
#define NNZ      500000
#define N_GRAPHS 50
#define IN_C     128
#define HID      256
#define OUT_C    2

#define SCAN_CHUNK 512
#define SCAN_NB    98    // 98*512 = 50176 >= 50000

// ---------------- device scratch (static, allocation-free) ----------------
__device__ int   g_is64;
__device__ int   g_deg_node[N_NODES];
__device__ int   g_deg_edge[N_EDGES];
__device__ int   g_ptr_node[N_NODES + 1];
__device__ int   g_ptr_edge[N_EDGES + 1];
__device__ int   g_cur_node[N_NODES];
__device__ int   g_cur_edge[N_EDGES];
__device__ int   g_adj_node[NNZ];
__device__ int   g_adj_edge[NNZ];
__device__ float g_dinv[N_NODES];
__device__ float g_binv[N_EDGES];
__device__ int   g_gstart[N_GRAPHS + 1];
__device__ int   g_part[2][SCAN_NB];
__device__ int   g_part_ex[2][SCAN_NB];
__device__ __half g_xw_h[(size_t)N_NODES * HID];   // GEMM output, fp16
__device__ __half g_e_h [(size_t)N_EDGES * HID];   // edge feats, fp16
__device__ float  g_h   [(size_t)N_NODES * HID];   // node feats, fp32 (GEMM input)
__device__ float  g_pooled[N_GRAPHS * HID];

__device__ __forceinline__ long long load_idx(const void* p, long long i, int is64) {
    return is64 ? ((const long long*)p)[i] : (long long)((const int*)p)[i];
}

// ---------------- index dtype detection (2048 samples) ----------------
__global__ void detect_kernel(const unsigned int* __restrict__ w) {
    __shared__ int any;
    if (threadIdx.x == 0) any = 0;
    __syncthreads();
    int nz = 0;
#pragma unroll
    for (int p = 0; p < 8; p++) {
        unsigned v = w[(threadIdx.x + p * 256) * 2 + 1];
        nz |= (v != 0);
    }
    if (nz) atomicOr(&any, 1);
    __syncthreads();
    if (threadIdx.x == 0) g_is64 = any ? 0 : 1;
}

__global__ void zero_kernel() {
    int i = blockIdx.x * blockDim.x + threadIdx.x;
    if (i < N_NODES) g_deg_node[i] = 0;
    if (i < N_EDGES) g_deg_edge[i] = 0;
}

__global__ void count_kernel(const void* __restrict__ ei) {
    int i = blockIdx.x * blockDim.x + threadIdx.x;
    if (i >= NNZ) return;
    int is64 = g_is64;
    int r = (int)load_idx(ei, i, is64);
    int c = (int)load_idx(ei, (long long)NNZ + i, is64);
    r = min(max(r, 0), N_NODES - 1);
    c = min(max(c, 0), N_EDGES - 1);
    atomicAdd(&g_deg_node[r], 1);
    atomicAdd(&g_deg_edge[c], 1);
}

// ---------------- parallel exclusive scan, 3 phases ----------------
__global__ void scan_part_kernel() {
    int which = blockIdx.y;
    const int* deg = which ? g_deg_edge : g_deg_node;
    int start = blockIdx.x * SCAN_CHUNK;
    int t = threadIdx.x;
    int base = start + t * 4;
    int sum = 0;
#pragma unroll
    for (int j = 0; j < 4; j++) {
        int i = base + j;
        if (i < N_NODES) sum += deg[i];
    }
    __shared__ int s[128];
    s[t] = sum;
    __syncthreads();
    for (int off = 64; off > 0; off >>= 1) {
        if (t < off) s[t] += s[t + off];
        __syncthreads();
    }
    if (t == 0) g_part[which][blockIdx.x] = s[0];
}

__global__ void scan_mid_kernel() {
    __shared__ int s[256];
    int t = threadIdx.x;
    int which = t >> 7;
    int j = t & 127;
    s[t] = (j < SCAN_NB) ? g_part[which][j] : 0;
    __syncthreads();
    for (int off = 1; off < 128; off <<= 1) {
        int v = (j >= off) ? s[t - off] : 0;
        __syncthreads();
        s[t] += v;
        __syncthreads();
    }
    if (j < SCAN_NB)
        g_part_ex[which][j] = (j > 0) ? s[t - 1] : 0;
    if (t == 0) { g_ptr_node[N_NODES] = NNZ; g_ptr_edge[N_EDGES] = NNZ; }
}

__global__ void scan_write_kernel() {
    int which = blockIdx.y;
    const int* deg = which ? g_deg_edge : g_deg_node;
    int* ptr = which ? g_ptr_edge : g_ptr_node;
    int* cur = which ? g_cur_edge : g_cur_node;
    float* inv = which ? g_binv : g_dinv;
    int start = blockIdx.x * SCAN_CHUNK;
    int t = threadIdx.x;
    int base = start + t * 4;
    int d[4];
    int sum = 0;
#pragma unroll
    for (int j = 0; j < 4; j++) {
        int i = base + j;
        d[j] = (i < N_NODES) ? deg[i] : 0;
        sum += d[j];
    }
    __shared__ int s[128];
    s[t] = sum;
    __syncthreads();
    for (int off = 1; off < 128; off <<= 1) {
        int v = (t >= off) ? s[t - off] : 0;
        __syncthreads();
        s[t] += v;
        __syncthreads();
    }
    int run = g_part_ex[which][blockIdx.x] + ((t > 0) ? s[t - 1] : 0);
#pragma unroll
    for (int j = 0; j < 4; j++) {
        int i = base + j;
        if (i < N_NODES) {
            ptr[i] = run;
            cur[i] = run;
            inv[i] = (d[j] > 0) ? 1.0f / (float)d[j] : 0.0f;
            run += d[j];
        }
    }
}

__global__ void fill_kernel(const void* __restrict__ ei) {
    int i = blockIdx.x * blockDim.x + threadIdx.x;
    if (i >= NNZ) return;
    int is64 = g_is64;
    int r = (int)load_idx(ei, i, is64);
    int c = (int)load_idx(ei, (long long)NNZ + i, is64);
    r = min(max(r, 0), N_NODES - 1);
    c = min(max(c, 0), N_EDGES - 1);
    int p = atomicAdd(&g_cur_edge[c], 1);
    if (p >= 0 && p < NNZ) g_adj_edge[p] = r;
    int q = atomicAdd(&g_cur_node[r], 1);
    if (q >= 0 && q < NNZ) g_adj_node[q] = c;
}

__global__ void gstart_kernel(const void* __restrict__ batch) {
    int i = blockIdx.x * blockDim.x + threadIdx.x;
    if (i >= N_NODES) return;
    int is64 = g_is64;
    long long b  = load_idx(batch, i, is64);
    long long bp = (i == 0) ? -1 : load_idx(batch, i - 1, is64);
    if (b  < 0) b  = 0;  if (b  > N_GRAPHS - 1) b  = N_GRAPHS - 1;
    if (bp < -1) bp = -1; if (bp > N_GRAPHS - 1) bp = N_GRAPHS - 1;
    if (b != bp)
        for (long long g = bp + 1; g <= b; g++) g_gstart[g] = i;
    if (i == N_NODES - 1)
        for (long long g = b + 1; g <= N_GRAPHS; g++) g_gstart[g] = N_NODES;
}

// ---------------- fp16 tensor-core GEMM (single term, fp32 accumulate) ----------------
// C[M,256] (fp16 out) = A[M,K] (fp32) * B[K,256] (fp32)
// block tile 128x128, BK=32, 8 warps, warp tile 64x32, mma.m16n8k16.f16

#define A_STRIDE 40   // halves per A smem row (32 data + 8 pad)
#define B_STRIDE 136  // halves per B smem row (128 data + 8 pad)

__device__ __forceinline__ unsigned pack_f16(float v0, float v1) {
    __half2 p = __floats2half2_rn(v0, v1);
    return *(unsigned*)&p;
}

__device__ __forceinline__ void ldmat4(unsigned* r, unsigned addr) {
    asm volatile("ldmatrix.sync.aligned.m8n8.x4.shared.b16 {%0,%1,%2,%3}, [%4];"
                 : "=r"(r[0]), "=r"(r[1]), "=r"(r[2]), "=r"(r[3]) : "r"(addr));
}
__device__ __forceinline__ void ldmat4t(unsigned* r, unsigned addr) {
    asm volatile("ldmatrix.sync.aligned.m8n8.x4.trans.shared.b16 {%0,%1,%2,%3}, [%4];"
                 : "=r"(r[0]), "=r"(r[1]), "=r"(r[2]), "=r"(r[3]) : "r"(addr));
}
__device__ __forceinline__ void mma16816(float* c, const unsigned* a, const unsigned* b) {
    asm volatile("mma.sync.aligned.m16n8k16.row.col.f32.f16.f16.f32 "
                 "{%0,%1,%2,%3}, {%4,%5,%6,%7}, {%8,%9}, {%0,%1,%2,%3};"
                 : "+f"(c[0]), "+f"(c[1]), "+f"(c[2]), "+f"(c[3])
                 : "r"(a[0]), "r"(a[1]), "r"(a[2]), "r"(a[3]), "r"(b[0]), "r"(b[1]));
}

__global__ __launch_bounds__(256) void mma_gemm_kernel(
    const float* __restrict__ A, const float* __restrict__ B,
    __half* __restrict__ C, int M, int K) {
    __shared__ unsigned As[128 * A_STRIDE / 2];
    __shared__ unsigned Bs[32 * B_STRIDE / 2];

    int t = threadIdx.x;
    int lane = t & 31;
    int warpid = t >> 5;
    int warp_m = (warpid & 1) * 64;
    int warp_n = (warpid >> 1) * 32;
    int bx = blockIdx.x, by = blockIdx.y;

    float acc[4][4][4];
#pragma unroll
    for (int i = 0; i < 4; i++)
#pragma unroll
        for (int j = 0; j < 4; j++)
#pragma unroll
            for (int k = 0; k < 4; k++) acc[i][j][k] = 0.f;

    int tt = lane >> 3, rr = lane & 7;
    unsigned a_base = (unsigned)__cvta_generic_to_shared(As);
    unsigned b_base = (unsigned)__cvta_generic_to_shared(Bs);

    for (int k0 = 0; k0 < K; k0 += 32) {
        // ---- stage A tile 128x32 fp32 -> fp16 ----
#pragma unroll
        for (int p = 0; p < 4; p++) {
            int f4_id = t + p * 256;
            int row = f4_id >> 3;
            int f4 = f4_id & 7;
            int grow = by * 128 + row;
            float4 v;
            if (grow < M) v = *(const float4*)(A + (size_t)grow * K + k0 + f4 * 4);
            else          v = make_float4(0.f, 0.f, 0.f, 0.f);
            int base = row * (A_STRIDE / 2) + f4 * 2;
            As[base]     = pack_f16(v.x, v.y);
            As[base + 1] = pack_f16(v.z, v.w);
        }
        // ---- stage B tile 32x128 fp32 -> fp16 ----
#pragma unroll
        for (int p = 0; p < 4; p++) {
            int f4_id = t + p * 256;
            int row = f4_id >> 5;
            int f4c = f4_id & 31;
            float4 v = *(const float4*)(B + (size_t)(k0 + row) * 256 + bx * 128 + f4c * 4);
            int base = row * (B_STRIDE / 2) + f4c * 2;
            Bs[base]     = pack_f16(v.x, v.y);
            Bs[base + 1] = pack_f16(v.z, v.w);
        }
        __syncthreads();

        // ---- compute 2 x k16 steps ----
#pragma unroll
        for (int ks = 0; ks < 2; ks++) {
            int k16 = ks * 16;
            unsigned a[4][4];
#pragma unroll
            for (int mf = 0; mf < 4; mf++) {
                int row = warp_m + mf * 16 + (tt & 1) * 8 + rr;
                int kk = k16 + (tt >> 1) * 8;
                ldmat4(a[mf], a_base + (unsigned)(row * A_STRIDE + kk) * 2);
            }
            unsigned b[4][2];
#pragma unroll
            for (int nf2 = 0; nf2 < 2; nf2++) {
                int row = k16 + (tt & 1) * 8 + rr;
                int col = warp_n + nf2 * 16 + (tt >> 1) * 8;
                unsigned rh[4];
                ldmat4t(rh, b_base + (unsigned)(row * B_STRIDE + col) * 2);
                b[nf2 * 2][0] = rh[0]; b[nf2 * 2][1] = rh[1];
                b[nf2 * 2 + 1][0] = rh[2]; b[nf2 * 2 + 1][1] = rh[3];
            }
#pragma unroll
            for (int mf = 0; mf < 4; mf++)
#pragma unroll
                for (int nf = 0; nf < 4; nf++)
                    mma16816(acc[mf][nf], a[mf], b[nf]);
        }
        __syncthreads();
    }

    // epilogue: fp32 acc -> fp16 out
    int g = lane >> 2, tg = lane & 3;
#pragma unroll
    for (int mf = 0; mf < 4; mf++) {
#pragma unroll
        for (int nf = 0; nf < 4; nf++) {
            int col = bx * 128 + warp_n + nf * 8 + tg * 2;
            int row0 = by * 128 + warp_m + mf * 16 + g;
            int row1 = row0 + 8;
            if (row0 < M)
                *(__half2*)(C + (size_t)row0 * 256 + col) = __floats2half2_rn(acc[mf][nf][0], acc[mf][nf][1]);
            if (row1 < M)
                *(__half2*)(C + (size_t)row1 * 256 + col) = __floats2half2_rn(acc[mf][nf][2], acc[mf][nf][3]);
        }
    }
}

// ---------------- gathers (CSR, no atomics), 1 warp per segment, fp16 rows ----------------
__global__ __launch_bounds__(256) void gather_edge_kernel() {
    int seg = blockIdx.x * 8 + threadIdx.y;
    int t = threadIdx.x;
    __shared__ int idx[8][32];
    int s = g_ptr_edge[seg], en = g_ptr_edge[seg + 1];
    s = min(max(s, 0), NNZ); en = min(max(en, s), NNZ);
    float2 a0 = make_float2(0,0), a1 = make_float2(0,0), a2 = make_float2(0,0), a3 = make_float2(0,0);
    for (int base = s; base < en; base += 32) {
        int cnt = min(32, en - base);
        if (t < cnt) idx[threadIdx.y][t] = g_adj_edge[base + t];
        __syncwarp();
        for (int j = 0; j < cnt; j++) {
            const uint4* row = (const uint4*)(g_xw_h + (size_t)idx[threadIdx.y][j] * HID);
            uint4 v = row[t];
            float2 f0 = __half22float2(*(__half2*)&v.x);
            float2 f1 = __half22float2(*(__half2*)&v.y);
            float2 f2 = __half22float2(*(__half2*)&v.z);
            float2 f3 = __half22float2(*(__half2*)&v.w);
            a0.x += f0.x; a0.y += f0.y; a1.x += f1.x; a1.y += f1.y;
            a2.x += f2.x; a2.y += f2.y; a3.x += f3.x; a3.y += f3.y;
        }
        __syncwarp();
    }
    float b = g_binv[seg];
    uint4 ov;
    *(__half2*)&ov.x = __floats2half2_rn(a0.x * b, a0.y * b);
    *(__half2*)&ov.y = __floats2half2_rn(a1.x * b, a1.y * b);
    *(__half2*)&ov.z = __floats2half2_rn(a2.x * b, a2.y * b);
    *(__half2*)&ov.w = __floats2half2_rn(a3.x * b, a3.y * b);
    ((uint4*)(g_e_h + (size_t)seg * HID))[t] = ov;
}

__global__ __launch_bounds__(256) void gather_node_kernel(const float* __restrict__ bias) {
    int seg = blockIdx.x * 8 + threadIdx.y;
    int t = threadIdx.x;
    __shared__ int idx[8][32];
    int s = g_ptr_node[seg], en = g_ptr_node[seg + 1];
    s = min(max(s, 0), NNZ); en = min(max(en, s), NNZ);
    float2 a0 = make_float2(0,0), a1 = make_float2(0,0), a2 = make_float2(0,0), a3 = make_float2(0,0);
    for (int base = s; base < en; base += 32) {
        int cnt = min(32, en - base);
        if (t < cnt) idx[threadIdx.y][t] = g_adj_node[base + t];
        __syncwarp();
        for (int j = 0; j < cnt; j++) {
            const uint4* row = (const uint4*)(g_e_h + (size_t)idx[threadIdx.y][j] * HID);
            uint4 v = row[t];
            float2 f0 = __half22float2(*(__half2*)&v.x);
            float2 f1 = __half22float2(*(__half2*)&v.y);
            float2 f2 = __half22float2(*(__half2*)&v.z);
            float2 f3 = __half22float2(*(__half2*)&v.w);
            a0.x += f0.x; a0.y += f0.y; a1.x += f1.x; a1.y += f1.y;
            a2.x += f2.x; a2.y += f2.y; a3.x += f3.x; a3.y += f3.y;
        }
        __syncwarp();
    }
    float d = g_dinv[seg];
    const float4* bz = (const float4*)(bias + 8 * t);
    float4 c0 = bz[0], c1 = bz[1];
    float* o = g_h + (size_t)seg * HID + 8 * t;
    *(float4*)(o) = make_float4(
        fmaxf(a0.x * d + c0.x, 0.f), fmaxf(a0.y * d + c0.y, 0.f),
        fmaxf(a1.x * d + c0.z, 0.f), fmaxf(a1.y * d + c0.w, 0.f));
    *(float4*)(o + 4) = make_float4(
        fmaxf(a2.x * d + c1.x, 0.f), fmaxf(a2.y * d + c1.y, 0.f),
        fmaxf(a3.x * d + c1.z, 0.f), fmaxf(a3.y * d + c1.w, 0.f));
}

__global__ __launch_bounds__(256) void pool_kernel() {
    int g = blockIdx.x, t = threadIdx.x;
    int s = g_gstart[g], e = g_gstart[g + 1];
    s = min(max(s, 0), N_NODES); e = min(max(e, s), N_NODES);
    float acc = 0.f;
    for (int i = s; i < e; i++) acc += g_h[(size_t)i * HID + t];
    int c = e - s;
    float inv = 1.0f / (float)max(c, 1);
    g_pooled[g * HID + t] = acc * inv;
}

__global__ __launch_bounds__(256) void mlp_kernel(
    const float* __restrict__ M1, const float* __restrict__ bM1,
    const float* __restrict__ M2, const float* __restrict__ bM2,
    float* __restrict__ out) {
    int g = blockIdx.x, t = threadIdx.x;
    __shared__ float p[HID];
    __shared__ float z[HID];
    __shared__ float red[HID];
    p[t] = g_pooled[g * HID + t];
    __syncthreads();
    float acc = bM1[t];
#pragma unroll 8
    for (int k = 0; k < HID; k++) acc += p[k] * M1[k * HID + t];
    z[t] = fmaxf(acc, 0.f);
    __syncthreads();
    for (int o = 0; o < OUT_C; o++) {
        red[t] = z[t] * M2[t * OUT_C + o];
        __syncthreads();
        for (int s = 128; s > 0; s >>= 1) {
            if (t < s) red[t] += red[t + s];
            __syncthreads();
        }
        if (t == 0) out[g * OUT_C + o] = red[0] + bM2[o];
        __syncthreads();
    }
}

// ---------------- launch ----------------
extern "C" void kernel_launch(void* const* d_in, const int* in_sizes, int n_in,
                              void* d_out, int out_size) {
    const float* x    = (const float*)d_in[0];
    const void*  ei   = d_in[1];
    const void*  batch= d_in[2];
    const float* W0   = (const float*)d_in[3];
    const float* b0   = (const float*)d_in[4];
    const float* W1   = (const float*)d_in[5];
    const float* b1   = (const float*)d_in[6];
    const float* W2   = (const float*)d_in[7];
    const float* b2   = (const float*)d_in[8];
    const float* M1   = (const float*)d_in[9];
    const float* bM1  = (const float*)d_in[10];
    const float* M2   = (const float*)d_in[11];
    const float* bM2  = (const float*)d_in[12];
    float* out = (float*)d_out;

    float*  hptr  = nullptr;
    __half* xwptr = nullptr;
    cudaGetSymbolAddress((void**)&hptr,  g_h);
    cudaGetSymbolAddress((void**)&xwptr, g_xw_h);

    detect_kernel<<<1, 256>>>((const unsigned int*)ei);
    zero_kernel<<<(N_NODES + 255) / 256, 256>>>();
    count_kernel<<<(NNZ + 255) / 256, 256>>>(ei);
    scan_part_kernel<<<dim3(SCAN_NB, 2), 128>>>();
    scan_mid_kernel<<<1, 256>>>();
    scan_write_kernel<<<dim3(SCAN_NB, 2), 128>>>();
    fill_kernel<<<(NNZ + 255) / 256, 256>>>(ei);
    gstart_kernel<<<(N_NODES + 255) / 256, 256>>>(batch);

    const float* Ws[3] = {W0, W1, W2};
    const float* bs[3] = {b0, b1, b2};
    const float* A = x;
    int K = IN_C;
    dim3 ggrid(2, (N_NODES + 127) / 128);
    dim3 gb(32, 8);
    for (int l = 0; l < 3; l++) {
        mma_gemm_kernel<<<ggrid, 256>>>(A, Ws[l], xwptr, N_NODES, K);
        gather_edge_kernel<<<N_EDGES / 8, gb>>>();
        gather_node_kernel<<<N_NODES / 8, gb>>>(bs[l]);
        A = hptr;
        K = HID;
    }
    pool_kernel<<<N_GRAPHS, 256>>>();
    mlp_kernel<<<N_GRAPHS, 256>>>(M1, bM1, M2, bM2, out);
}

// round 12
// speedup vs baseline: 4.2169x; 1.1649x over previous
#include <cuda_runtime.h>
#include <cuda_fp16.h>

#define N_NODES  50000
#define N_EDGES  50000
#define NNZ      500000
#define N_GRAPHS 50
#define IN_C     128
#define HID      256
#define OUT_C    2

#define SCAN_CHUNK 512
#define SCAN_NB    98    // 98*512 = 50176 >= 50000

// ---------------- device scratch (static, allocation-free) ----------------
__device__ int   g_is64;
__device__ int   g_deg_node[N_NODES];
__device__ int   g_deg_edge[N_EDGES];
__device__ int   g_ptr_node[N_NODES + 1];
__device__ int   g_ptr_edge[N_EDGES + 1];
__device__ int   g_cur_node[N_NODES];
__device__ int   g_cur_edge[N_EDGES];
__device__ int   g_adj_node[NNZ];
__device__ int   g_adj_edge[NNZ];
__device__ float g_dinv[N_NODES];
__device__ float g_binv[N_EDGES];
__device__ int   g_gstart[N_GRAPHS + 1];
__device__ int   g_part[2][SCAN_NB];
__device__ int   g_part_ex[2][SCAN_NB];
__device__ __half g_x_h [(size_t)N_NODES * IN_C];  // input x, fp16
__device__ __half g_w_h [3][HID * HID];            // weights fp16 (W0 uses first 128*256)
__device__ __half g_xw_h[(size_t)N_NODES * HID];   // GEMM output, fp16
__device__ __half g_e_h [(size_t)N_EDGES * HID];   // edge feats, fp16
__device__ __half g_h_h [(size_t)N_NODES * HID];   // node feats, fp16 (GEMM input)

__device__ __forceinline__ long long load_idx(const void* p, long long i, int is64) {
    return is64 ? ((const long long*)p)[i] : (long long)((const int*)p)[i];
}

// ---------------- init: zero degree arrays + index dtype detection ----------------
__global__ void init_kernel(const unsigned int* __restrict__ w) {
    int i = blockIdx.x * blockDim.x + threadIdx.x;
    if (i < N_NODES) g_deg_node[i] = 0;
    if (i < N_EDGES) g_deg_edge[i] = 0;
    if (blockIdx.x == 0) {
        __shared__ int any;
        if (threadIdx.x == 0) any = 0;
        __syncthreads();
        int nz = 0;
#pragma unroll
        for (int p = 0; p < 8; p++) {
            unsigned v = w[(threadIdx.x + p * 256) * 2 + 1];
            nz |= (v != 0);
        }
        if (nz) atomicOr(&any, 1);
        __syncthreads();
        if (threadIdx.x == 0) g_is64 = any ? 0 : 1;
    }
}

// ---------------- fused fp32->fp16 conversion: x, W0, W1, W2 ----------------
#define XU  (N_NODES * IN_C / 4)   // 1600000 float4 units
#define W0U (IN_C * HID / 4)       // 8192
#define WU  (HID * HID / 4)        // 16384
#define CONVU (XU + W0U + 2 * WU)

__global__ void conv_kernel(const float* __restrict__ x, const float* __restrict__ W0,
                            const float* __restrict__ W1, const float* __restrict__ W2) {
    long long id = (long long)blockIdx.x * blockDim.x + threadIdx.x;
    if (id >= CONVU) return;
    const float* src;
    __half* dst;
    long long off;
    if (id < XU)                { src = x;  dst = g_x_h;    off = id; }
    else if (id < XU + W0U)     { src = W0; dst = g_w_h[0]; off = id - XU; }
    else if (id < XU + W0U + WU){ src = W1; dst = g_w_h[1]; off = id - XU - W0U; }
    else                        { src = W2; dst = g_w_h[2]; off = id - XU - W0U - WU; }
    float4 v = ((const float4*)src)[off];
    __half2 h0 = __floats2half2_rn(v.x, v.y);
    __half2 h1 = __floats2half2_rn(v.z, v.w);
    ((uint2*)dst)[off] = make_uint2(*(unsigned*)&h0, *(unsigned*)&h1);
}

__global__ void count_kernel(const void* __restrict__ ei) {
    int i = blockIdx.x * blockDim.x + threadIdx.x;
    if (i >= NNZ) return;
    int is64 = g_is64;
    int r = (int)load_idx(ei, i, is64);
    int c = (int)load_idx(ei, (long long)NNZ + i, is64);
    r = min(max(r, 0), N_NODES - 1);
    c = min(max(c, 0), N_EDGES - 1);
    atomicAdd(&g_deg_node[r], 1);
    atomicAdd(&g_deg_edge[c], 1);
}

// ---------------- parallel exclusive scan, 3 phases ----------------
__global__ void scan_part_kernel() {
    int which = blockIdx.y;
    const int* deg = which ? g_deg_edge : g_deg_node;
    int start = blockIdx.x * SCAN_CHUNK;
    int t = threadIdx.x;
    int base = start + t * 4;
    int sum = 0;
#pragma unroll
    for (int j = 0; j < 4; j++) {
        int i = base + j;
        if (i < N_NODES) sum += deg[i];
    }
    __shared__ int s[128];
    s[t] = sum;
    __syncthreads();
    for (int off = 64; off > 0; off >>= 1) {
        if (t < off) s[t] += s[t + off];
        __syncthreads();
    }
    if (t == 0) g_part[which][blockIdx.x] = s[0];
}

__global__ void scan_mid_kernel() {
    __shared__ int s[256];
    int t = threadIdx.x;
    int which = t >> 7;
    int j = t & 127;
    s[t] = (j < SCAN_NB) ? g_part[which][j] : 0;
    __syncthreads();
    for (int off = 1; off < 128; off <<= 1) {
        int v = (j >= off) ? s[t - off] : 0;
        __syncthreads();
        s[t] += v;
        __syncthreads();
    }
    if (j < SCAN_NB)
        g_part_ex[which][j] = (j > 0) ? s[t - 1] : 0;
    if (t == 0) { g_ptr_node[N_NODES] = NNZ; g_ptr_edge[N_EDGES] = NNZ; }
}

__global__ void scan_write_kernel() {
    int which = blockIdx.y;
    const int* deg = which ? g_deg_edge : g_deg_node;
    int* ptr = which ? g_ptr_edge : g_ptr_node;
    int* cur = which ? g_cur_edge : g_cur_node;
    float* inv = which ? g_binv : g_dinv;
    int start = blockIdx.x * SCAN_CHUNK;
    int t = threadIdx.x;
    int base = start + t * 4;
    int d[4];
    int sum = 0;
#pragma unroll
    for (int j = 0; j < 4; j++) {
        int i = base + j;
        d[j] = (i < N_NODES) ? deg[i] : 0;
        sum += d[j];
    }
    __shared__ int s[128];
    s[t] = sum;
    __syncthreads();
    for (int off = 1; off < 128; off <<= 1) {
        int v = (t >= off) ? s[t - off] : 0;
        __syncthreads();
        s[t] += v;
        __syncthreads();
    }
    int run = g_part_ex[which][blockIdx.x] + ((t > 0) ? s[t - 1] : 0);
#pragma unroll
    for (int j = 0; j < 4; j++) {
        int i = base + j;
        if (i < N_NODES) {
            ptr[i] = run;
            cur[i] = run;
            inv[i] = (d[j] > 0) ? 1.0f / (float)d[j] : 0.0f;
            run += d[j];
        }
    }
}

__global__ void fill_kernel(const void* __restrict__ ei) {
    int i = blockIdx.x * blockDim.x + threadIdx.x;
    if (i >= NNZ) return;
    int is64 = g_is64;
    int r = (int)load_idx(ei, i, is64);
    int c = (int)load_idx(ei, (long long)NNZ + i, is64);
    r = min(max(r, 0), N_NODES - 1);
    c = min(max(c, 0), N_EDGES - 1);
    int p = atomicAdd(&g_cur_edge[c], 1);
    if (p >= 0 && p < NNZ) g_adj_edge[p] = r;
    int q = atomicAdd(&g_cur_node[r], 1);
    if (q >= 0 && q < NNZ) g_adj_node[q] = c;
}

__global__ void gstart_kernel(const void* __restrict__ batch) {
    int i = blockIdx.x * blockDim.x + threadIdx.x;
    if (i >= N_NODES) return;
    int is64 = g_is64;
    long long b  = load_idx(batch, i, is64);
    long long bp = (i == 0) ? -1 : load_idx(batch, i - 1, is64);
    if (b  < 0) b  = 0;  if (b  > N_GRAPHS - 1) b  = N_GRAPHS - 1;
    if (bp < -1) bp = -1; if (bp > N_GRAPHS - 1) bp = N_GRAPHS - 1;
    if (b != bp)
        for (long long g = bp + 1; g <= b; g++) g_gstart[g] = i;
    if (i == N_NODES - 1)
        for (long long g = b + 1; g <= N_GRAPHS; g++) g_gstart[g] = N_NODES;
}

// ---------------- fp16 tensor-core GEMM, double-buffered ----------------
// C[M,256] (fp16) = A[M,K] (fp16) * B[K,256] (fp16)
// block tile 128x128, BK=32, 8 warps, warp tile 64x32, mma.m16n8k16.f16

#define A_ST 20   // uints per A smem row (40 halves: 32 data + 8 pad)
#define B_ST 68   // uints per B smem row (136 halves: 128 data + 8 pad)

__device__ __forceinline__ void ldmat4(unsigned* r, unsigned addr) {
    asm volatile("ldmatrix.sync.aligned.m8n8.x4.shared.b16 {%0,%1,%2,%3}, [%4];"
                 : "=r"(r[0]), "=r"(r[1]), "=r"(r[2]), "=r"(r[3]) : "r"(addr));
}
__device__ __forceinline__ void ldmat4t(unsigned* r, unsigned addr) {
    asm volatile("ldmatrix.sync.aligned.m8n8.x4.trans.shared.b16 {%0,%1,%2,%3}, [%4];"
                 : "=r"(r[0]), "=r"(r[1]), "=r"(r[2]), "=r"(r[3]) : "r"(addr));
}
__device__ __forceinline__ void mma16816(float* c, const unsigned* a, const unsigned* b) {
    asm volatile("mma.sync.aligned.m16n8k16.row.col.f32.f16.f16.f32 "
                 "{%0,%1,%2,%3}, {%4,%5,%6,%7}, {%8,%9}, {%0,%1,%2,%3};"
                 : "+f"(c[0]), "+f"(c[1]), "+f"(c[2]), "+f"(c[3])
                 : "r"(a[0]), "r"(a[1]), "r"(a[2]), "r"(a[3]), "r"(b[0]), "r"(b[1]));
}

__global__ __launch_bounds__(256) void mma_gemm_kernel(
    const __half* __restrict__ A, const __half* __restrict__ B,
    __half* __restrict__ C, int M, int K) {
    __shared__ unsigned As[2][128 * A_ST];
    __shared__ unsigned Bs[2][32 * B_ST];

    int t = threadIdx.x;
    int lane = t & 31;
    int warpid = t >> 5;
    int warp_m = (warpid & 1) * 64;
    int warp_n = (warpid >> 1) * 32;
    int bx = blockIdx.x, by = blockIdx.y;

    float acc[4][4][4];
#pragma unroll
    for (int i = 0; i < 4; i++)
#pragma unroll
        for (int j = 0; j < 4; j++)
#pragma unroll
            for (int k = 0; k < 4; k++) acc[i][j][k] = 0.f;

    int tt = lane >> 3, rr = lane & 7;
    unsigned a_base0 = (unsigned)__cvta_generic_to_shared(&As[0][0]);
    unsigned b_base0 = (unsigned)__cvta_generic_to_shared(&Bs[0][0]);

    // staging geometry
    int arow = t >> 1;                 // 0..127
    int aseg = t & 1;                  // 16-half segment within 32
    int grow = by * 128 + arow;
    bool aok = grow < M;
    const __half* Arow = A + (size_t)grow * K + aseg * 16;
    int brow = t >> 3;                 // 0..31
    int bseg = t & 7;                  // 16-half segment within 128
    const __half* Bp = B + bx * 128 + bseg * 16;

    uint4 av0, av1, bv0, bv1;

#define LOAD_TILE(k0) do { \
        if (aok) { av0 = *(const uint4*)(Arow + (k0)); av1 = *(const uint4*)(Arow + (k0) + 8); } \
        else { av0 = make_uint4(0,0,0,0); av1 = av0; } \
        const __half* _bp = Bp + (size_t)((k0) + brow) * 256; \
        bv0 = *(const uint4*)_bp; bv1 = *(const uint4*)(_bp + 8); \
    } while (0)

#define STORE_TILE(buf) do { \
        unsigned* as = &As[buf][arow * A_ST + aseg * 8]; \
        *(uint2*)(as)     = make_uint2(av0.x, av0.y); \
        *(uint2*)(as + 2) = make_uint2(av0.z, av0.w); \
        *(uint2*)(as + 4) = make_uint2(av1.x, av1.y); \
        *(uint2*)(as + 6) = make_uint2(av1.z, av1.w); \
        unsigned* bs = &Bs[buf][brow * B_ST + bseg * 8]; \
        *(uint4*)(bs)     = bv0; \
        *(uint4*)(bs + 4) = bv1; \
    } while (0)

#define COMPUTE(buf) do { \
        unsigned a_base = a_base0 + (buf) * (128 * A_ST * 4); \
        unsigned b_base = b_base0 + (buf) * (32 * B_ST * 4); \
        _Pragma("unroll") \
        for (int ks = 0; ks < 2; ks++) { \
            int k16 = ks * 16; \
            unsigned a[4][4]; \
            _Pragma("unroll") \
            for (int mf = 0; mf < 4; mf++) { \
                int row = warp_m + mf * 16 + (tt & 1) * 8 + rr; \
                int kk = k16 + (tt >> 1) * 8; \
                ldmat4(a[mf], a_base + (unsigned)(row * (A_ST * 2) + kk) * 2); \
            } \
            unsigned b[4][2]; \
            _Pragma("unroll") \
            for (int nf2 = 0; nf2 < 2; nf2++) { \
                int row = k16 + (tt & 1) * 8 + rr; \
                int col = warp_n + nf2 * 16 + (tt >> 1) * 8; \
                unsigned rh[4]; \
                ldmat4t(rh, b_base + (unsigned)(row * (B_ST * 2) + col) * 2); \
                b[nf2 * 2][0] = rh[0]; b[nf2 * 2][1] = rh[1]; \
                b[nf2 * 2 + 1][0] = rh[2]; b[nf2 * 2 + 1][1] = rh[3]; \
            } \
            _Pragma("unroll") \
            for (int mf = 0; mf < 4; mf++) \
                _Pragma("unroll") \
                for (int nf = 0; nf < 4; nf++) \
                    mma16816(acc[mf][nf], a[mf], b[nf]); \
        } \
    } while (0)

    LOAD_TILE(0);
    STORE_TILE(0);
    __syncthreads();
    int buf = 0;
    for (int k0 = 32; k0 < K; k0 += 32) {
        LOAD_TILE(k0);
        COMPUTE(buf);
        STORE_TILE(buf ^ 1);
        __syncthreads();
        buf ^= 1;
    }
    COMPUTE(buf);

    // epilogue: fp32 acc -> fp16 out
    int g = lane >> 2, tg = lane & 3;
#pragma unroll
    for (int mf = 0; mf < 4; mf++) {
#pragma unroll
        for (int nf = 0; nf < 4; nf++) {
            int col = bx * 128 + warp_n + nf * 8 + tg * 2;
            int row0 = by * 128 + warp_m + mf * 16 + g;
            int row1 = row0 + 8;
            if (row0 < M)
                *(__half2*)(C + (size_t)row0 * 256 + col) = __floats2half2_rn(acc[mf][nf][0], acc[mf][nf][1]);
            if (row1 < M)
                *(__half2*)(C + (size_t)row1 * 256 + col) = __floats2half2_rn(acc[mf][nf][2], acc[mf][nf][3]);
        }
    }
}

// ---------------- gathers (CSR, no atomics), 1 warp per segment, fp16 rows ----------------
__global__ __launch_bounds__(256) void gather_edge_kernel() {
    int seg = blockIdx.x * 8 + threadIdx.y;
    int t = threadIdx.x;
    __shared__ int idx[8][32];
    int s = g_ptr_edge[seg], en = g_ptr_edge[seg + 1];
    s = min(max(s, 0), NNZ); en = min(max(en, s), NNZ);
    float2 a0 = make_float2(0,0), a1 = make_float2(0,0), a2 = make_float2(0,0), a3 = make_float2(0,0);
    for (int base = s; base < en; base += 32) {
        int cnt = min(32, en - base);
        if (t < cnt) idx[threadIdx.y][t] = g_adj_edge[base + t];
        __syncwarp();
        for (int j = 0; j < cnt; j++) {
            const uint4* row = (const uint4*)(g_xw_h + (size_t)idx[threadIdx.y][j] * HID);
            uint4 v = row[t];
            float2 f0 = __half22float2(*(__half2*)&v.x);
            float2 f1 = __half22float2(*(__half2*)&v.y);
            float2 f2 = __half22float2(*(__half2*)&v.z);
            float2 f3 = __half22float2(*(__half2*)&v.w);
            a0.x += f0.x; a0.y += f0.y; a1.x += f1.x; a1.y += f1.y;
            a2.x += f2.x; a2.y += f2.y; a3.x += f3.x; a3.y += f3.y;
        }
        __syncwarp();
    }
    float b = g_binv[seg];
    uint4 ov;
    *(__half2*)&ov.x = __floats2half2_rn(a0.x * b, a0.y * b);
    *(__half2*)&ov.y = __floats2half2_rn(a1.x * b, a1.y * b);
    *(__half2*)&ov.z = __floats2half2_rn(a2.x * b, a2.y * b);
    *(__half2*)&ov.w = __floats2half2_rn(a3.x * b, a3.y * b);
    ((uint4*)(g_e_h + (size_t)seg * HID))[t] = ov;
}

__global__ __launch_bounds__(256) void gather_node_kernel(const float* __restrict__ bias) {
    int seg = blockIdx.x * 8 + threadIdx.y;
    int t = threadIdx.x;
    __shared__ int idx[8][32];
    int s = g_ptr_node[seg], en = g_ptr_node[seg + 1];
    s = min(max(s, 0), NNZ); en = min(max(en, s), NNZ);
    float2 a0 = make_float2(0,0), a1 = make_float2(0,0), a2 = make_float2(0,0), a3 = make_float2(0,0);
    for (int base = s; base < en; base += 32) {
        int cnt = min(32, en - base);
        if (t < cnt) idx[threadIdx.y][t] = g_adj_node[base + t];
        __syncwarp();
        for (int j = 0; j < cnt; j++) {
            const uint4* row = (const uint4*)(g_e_h + (size_t)idx[threadIdx.y][j] * HID);
            uint4 v = row[t];
            float2 f0 = __half22float2(*(__half2*)&v.x);
            float2 f1 = __half22float2(*(__half2*)&v.y);
            float2 f2 = __half22float2(*(__half2*)&v.z);
            float2 f3 = __half22float2(*(__half2*)&v.w);
            a0.x += f0.x; a0.y += f0.y; a1.x += f1.x; a1.y += f1.y;
            a2.x += f2.x; a2.y += f2.y; a3.x += f3.x; a3.y += f3.y;
        }
        __syncwarp();
    }
    float d = g_dinv[seg];
    const float4* bz = (const float4*)(bias + 8 * t);
    float4 c0 = bz[0], c1 = bz[1];
    uint4 ov;
    *(__half2*)&ov.x = __floats2half2_rn(fmaxf(a0.x * d + c0.x, 0.f), fmaxf(a0.y * d + c0.y, 0.f));
    *(__half2*)&ov.y = __floats2half2_rn(fmaxf(a1.x * d + c0.z, 0.f), fmaxf(a1.y * d + c0.w, 0.f));
    *(__half2*)&ov.z = __floats2half2_rn(fmaxf(a2.x * d + c1.x, 0.f), fmaxf(a2.y * d + c1.y, 0.f));
    *(__half2*)&ov.w = __floats2half2_rn(fmaxf(a3.x * d + c1.z, 0.f), fmaxf(a3.y * d + c1.w, 0.f));
    ((uint4*)(g_h_h + (size_t)seg * HID))[t] = ov;
}

// ---------------- fused pool + MLP head ----------------
__global__ __launch_bounds__(256) void pool_mlp_kernel(
    const float* __restrict__ M1, const float* __restrict__ bM1,
    const float* __restrict__ M2, const float* __restrict__ bM2,
    float* __restrict__ out) {
    int g = blockIdx.x, t = threadIdx.x;
    int s = g_gstart[g], e = g_gstart[g + 1];
    s = min(max(s, 0), N_NODES); e = min(max(e, s), N_NODES);
    float acc = 0.f;
    for (int i = s; i < e; i++)
        acc += __half2float(g_h_h[(size_t)i * HID + t]);
    __shared__ float p[HID];
    __shared__ float z[HID];
    __shared__ float red[HID];
    p[t] = acc / (float)max(e - s, 1);
    __syncthreads();
    float a2 = bM1[t];
#pragma unroll 8
    for (int k = 0; k < HID; k++) a2 += p[k] * M1[k * HID + t];
    z[t] = fmaxf(a2, 0.f);
    __syncthreads();
    for (int o = 0; o < OUT_C; o++) {
        red[t] = z[t] * M2[t * OUT_C + o];
        __syncthreads();
        for (int ss = 128; ss > 0; ss >>= 1) {
            if (t < ss) red[t] += red[t + ss];
            __syncthreads();
        }
        if (t == 0) out[g * OUT_C + o] = red[0] + bM2[o];
        __syncthreads();
    }
}

// ---------------- launch ----------------
extern "C" void kernel_launch(void* const* d_in, const int* in_sizes, int n_in,
                              void* d_out, int out_size) {
    const float* x    = (const float*)d_in[0];
    const void*  ei   = d_in[1];
    const void*  batch= d_in[2];
    const float* W0   = (const float*)d_in[3];
    const float* b0   = (const float*)d_in[4];
    const float* W1   = (const float*)d_in[5];
    const float* b1   = (const float*)d_in[6];
    const float* W2   = (const float*)d_in[7];
    const float* b2   = (const float*)d_in[8];
    const float* M1   = (const float*)d_in[9];
    const float* bM1  = (const float*)d_in[10];
    const float* M2   = (const float*)d_in[11];
    const float* bM2  = (const float*)d_in[12];
    float* out = (float*)d_out;

    __half *xh = nullptr, *wh = nullptr, *xwptr = nullptr, *hh = nullptr;
    cudaGetSymbolAddress((void**)&xh,    g_x_h);
    cudaGetSymbolAddress((void**)&wh,    g_w_h);
    cudaGetSymbolAddress((void**)&xwptr, g_xw_h);
    cudaGetSymbolAddress((void**)&hh,    g_h_h);

    init_kernel<<<196, 256>>>((const unsigned int*)ei);
    conv_kernel<<<(CONVU + 255) / 256, 256>>>(x, W0, W1, W2);
    count_kernel<<<(NNZ + 255) / 256, 256>>>(ei);
    scan_part_kernel<<<dim3(SCAN_NB, 2), 128>>>();
    scan_mid_kernel<<<1, 256>>>();
    scan_write_kernel<<<dim3(SCAN_NB, 2), 128>>>();
    fill_kernel<<<(NNZ + 255) / 256, 256>>>(ei);
    gstart_kernel<<<(N_NODES + 255) / 256, 256>>>(batch);

    const float* bs[3] = {b0, b1, b2};
    const __half* A = xh;
    int K = IN_C;
    dim3 ggrid(2, (N_NODES + 127) / 128);
    dim3 gb(32, 8);
    for (int l = 0; l < 3; l++) {
        mma_gemm_kernel<<<ggrid, 256>>>(A, wh + (size_t)l * HID * HID, xwptr, N_NODES, K);
        gather_edge_kernel<<<N_EDGES / 8, gb>>>();
        gather_node_kernel<<<N_NODES / 8, gb>>>(bs[l]);
        A = hh;
        K = HID;
    }
    pool_mlp_kernel<<<N_GRAPHS, 256>>>(M1, bM1, M2, bM2, out);
}

// round 13
// speedup vs baseline: 4.4179x; 1.0477x over previous
#include <cuda_runtime.h>
#include <cuda_fp16.h>

#define N_NODES  50000
#define N_EDGES  50000
#define NNZ      500000
#define N_GRAPHS 50
#define IN_C     128
#define HID      256
#define OUT_C    2

#define SCAN_CHUNK 512
#define SCAN_NB    98    // 98*512 = 50176 >= 50000

// ---------------- device scratch (static, allocation-free) ----------------
__device__ int   g_is64;
__device__ int   g_deg_node[N_NODES];
__device__ int   g_deg_edge[N_EDGES];
__device__ int   g_ptr_node[N_NODES + 1];
__device__ int   g_ptr_edge[N_EDGES + 1];
__device__ int   g_cur_node[N_NODES];
__device__ int   g_cur_edge[N_EDGES];
__device__ int   g_adj_node[NNZ];
__device__ int   g_adj_edge[NNZ];
__device__ float g_dinv[N_NODES];
__device__ float g_binv[N_EDGES];
__device__ int   g_gstart[N_GRAPHS + 1];
__device__ int   g_part[2][SCAN_NB];
__device__ int   g_part_ex[2][SCAN_NB];
__device__ __half g_x_h [(size_t)N_NODES * IN_C];  // input x, fp16
__device__ __half g_w_h [3][HID * HID];            // weights fp16 (W0 uses first 128*256)
__device__ __half g_xw_h[(size_t)N_NODES * HID];   // GEMM output, fp16
__device__ __half g_e_h [(size_t)N_EDGES * HID];   // edge feats, fp16
__device__ __half g_h_h [(size_t)N_NODES * HID];   // node feats, fp16 (GEMM input)
__device__ float  g_pooled[N_GRAPHS * HID];

__device__ __forceinline__ long long load_idx(const void* p, long long i, int is64) {
    return is64 ? ((const long long*)p)[i] : (long long)((const int*)p)[i];
}

// ---------------- init: zero deg arrays + pooled + index dtype detection ----------------
__global__ void init_kernel(const unsigned int* __restrict__ w) {
    int i = blockIdx.x * blockDim.x + threadIdx.x;
    if (i < N_NODES) g_deg_node[i] = 0;
    if (i < N_EDGES) g_deg_edge[i] = 0;
    if (i < N_GRAPHS * HID) g_pooled[i] = 0.f;
    if (blockIdx.x == 0) {
        __shared__ int any;
        if (threadIdx.x == 0) any = 0;
        __syncthreads();
        int nz = 0;
#pragma unroll
        for (int p = 0; p < 8; p++) {
            unsigned v = w[(threadIdx.x + p * 256) * 2 + 1];
            nz |= (v != 0);
        }
        if (nz) atomicOr(&any, 1);
        __syncthreads();
        if (threadIdx.x == 0) g_is64 = any ? 0 : 1;
    }
}

// ---------------- fused setup: conv (x,W->fp16) + count + gstart ----------------
#define XU  (N_NODES * IN_C / 4)   // 1600000 float4 units
#define W0U (IN_C * HID / 4)       // 8192
#define WU  (HID * HID / 4)        // 16384
#define CONVU (XU + W0U + 2 * WU)  // 1640960
#define CONV_NB  (CONVU / 256)               // 6410
#define COUNT_NB ((NNZ + 255) / 256)         // 1954
#define GST_NB   ((N_NODES + 255) / 256)     // 196
#define SETUP_NB (CONV_NB + COUNT_NB + GST_NB)

__global__ void setup_kernel(const float* __restrict__ x, const float* __restrict__ W0,
                             const float* __restrict__ W1, const float* __restrict__ W2,
                             const void* __restrict__ ei, const void* __restrict__ batch) {
    int blk = blockIdx.x;
    if (blk < CONV_NB) {
        long long id = (long long)blk * 256 + threadIdx.x;
        const float* src;
        __half* dst;
        long long off;
        if (id < XU)                 { src = x;  dst = g_x_h;    off = id; }
        else if (id < XU + W0U)      { src = W0; dst = g_w_h[0]; off = id - XU; }
        else if (id < XU + W0U + WU) { src = W1; dst = g_w_h[1]; off = id - XU - W0U; }
        else                         { src = W2; dst = g_w_h[2]; off = id - XU - W0U - WU; }
        float4 v = ((const float4*)src)[off];
        __half2 h0 = __floats2half2_rn(v.x, v.y);
        __half2 h1 = __floats2half2_rn(v.z, v.w);
        ((uint2*)dst)[off] = make_uint2(*(unsigned*)&h0, *(unsigned*)&h1);
        return;
    }
    blk -= CONV_NB;
    if (blk < COUNT_NB) {
        int i = blk * 256 + threadIdx.x;
        if (i >= NNZ) return;
        int is64 = g_is64;
        int r = (int)load_idx(ei, i, is64);
        int c = (int)load_idx(ei, (long long)NNZ + i, is64);
        r = min(max(r, 0), N_NODES - 1);
        c = min(max(c, 0), N_EDGES - 1);
        atomicAdd(&g_deg_node[r], 1);
        atomicAdd(&g_deg_edge[c], 1);
        return;
    }
    blk -= COUNT_NB;
    {
        int i = blk * 256 + threadIdx.x;
        if (i >= N_NODES) return;
        int is64 = g_is64;
        long long b  = load_idx(batch, i, is64);
        long long bp = (i == 0) ? -1 : load_idx(batch, i - 1, is64);
        if (b  < 0) b  = 0;  if (b  > N_GRAPHS - 1) b  = N_GRAPHS - 1;
        if (bp < -1) bp = -1; if (bp > N_GRAPHS - 1) bp = N_GRAPHS - 1;
        if (b != bp)
            for (long long g = bp + 1; g <= b; g++) g_gstart[g] = i;
        if (i == N_NODES - 1)
            for (long long g = b + 1; g <= N_GRAPHS; g++) g_gstart[g] = N_NODES;
    }
}

// ---------------- parallel exclusive scan, 3 phases ----------------
__global__ void scan_part_kernel() {
    int which = blockIdx.y;
    const int* deg = which ? g_deg_edge : g_deg_node;
    int start = blockIdx.x * SCAN_CHUNK;
    int t = threadIdx.x;
    int base = start + t * 4;
    int sum = 0;
#pragma unroll
    for (int j = 0; j < 4; j++) {
        int i = base + j;
        if (i < N_NODES) sum += deg[i];
    }
    __shared__ int s[128];
    s[t] = sum;
    __syncthreads();
    for (int off = 64; off > 0; off >>= 1) {
        if (t < off) s[t] += s[t + off];
        __syncthreads();
    }
    if (t == 0) g_part[which][blockIdx.x] = s[0];
}

__global__ void scan_mid_kernel() {
    __shared__ int s[256];
    int t = threadIdx.x;
    int which = t >> 7;
    int j = t & 127;
    s[t] = (j < SCAN_NB) ? g_part[which][j] : 0;
    __syncthreads();
    for (int off = 1; off < 128; off <<= 1) {
        int v = (j >= off) ? s[t - off] : 0;
        __syncthreads();
        s[t] += v;
        __syncthreads();
    }
    if (j < SCAN_NB)
        g_part_ex[which][j] = (j > 0) ? s[t - 1] : 0;
    if (t == 0) { g_ptr_node[N_NODES] = NNZ; g_ptr_edge[N_EDGES] = NNZ; }
}

__global__ void scan_write_kernel() {
    int which = blockIdx.y;
    const int* deg = which ? g_deg_edge : g_deg_node;
    int* ptr = which ? g_ptr_edge : g_ptr_node;
    int* cur = which ? g_cur_edge : g_cur_node;
    float* inv = which ? g_binv : g_dinv;
    int start = blockIdx.x * SCAN_CHUNK;
    int t = threadIdx.x;
    int base = start + t * 4;
    int d[4];
    int sum = 0;
#pragma unroll
    for (int j = 0; j < 4; j++) {
        int i = base + j;
        d[j] = (i < N_NODES) ? deg[i] : 0;
        sum += d[j];
    }
    __shared__ int s[128];
    s[t] = sum;
    __syncthreads();
    for (int off = 1; off < 128; off <<= 1) {
        int v = (t >= off) ? s[t - off] : 0;
        __syncthreads();
        s[t] += v;
        __syncthreads();
    }
    int run = g_part_ex[which][blockIdx.x] + ((t > 0) ? s[t - 1] : 0);
#pragma unroll
    for (int j = 0; j < 4; j++) {
        int i = base + j;
        if (i < N_NODES) {
            ptr[i] = run;
            cur[i] = run;
            inv[i] = (d[j] > 0) ? 1.0f / (float)d[j] : 0.0f;
            run += d[j];
        }
    }
}

__global__ void fill_kernel(const void* __restrict__ ei) {
    int i = blockIdx.x * blockDim.x + threadIdx.x;
    if (i >= NNZ) return;
    int is64 = g_is64;
    int r = (int)load_idx(ei, i, is64);
    int c = (int)load_idx(ei, (long long)NNZ + i, is64);
    r = min(max(r, 0), N_NODES - 1);
    c = min(max(c, 0), N_EDGES - 1);
    int p = atomicAdd(&g_cur_edge[c], 1);
    if (p >= 0 && p < NNZ) g_adj_edge[p] = r;
    int q = atomicAdd(&g_cur_node[r], 1);
    if (q >= 0 && q < NNZ) g_adj_node[q] = c;
}

// ---------------- fp16 tensor-core GEMM, double-buffered ----------------
// C[M,256] (fp16) = A[M,K] (fp16) * B[K,256] (fp16)
// block tile 128x128, BK=32, 8 warps, warp tile 64x32, mma.m16n8k16.f16

#define A_ST 20   // uints per A smem row (40 halves: 32 data + 8 pad)
#define B_ST 68   // uints per B smem row (136 halves: 128 data + 8 pad)

__device__ __forceinline__ void ldmat4(unsigned* r, unsigned addr) {
    asm volatile("ldmatrix.sync.aligned.m8n8.x4.shared.b16 {%0,%1,%2,%3}, [%4];"
                 : "=r"(r[0]), "=r"(r[1]), "=r"(r[2]), "=r"(r[3]) : "r"(addr));
}
__device__ __forceinline__ void ldmat4t(unsigned* r, unsigned addr) {
    asm volatile("ldmatrix.sync.aligned.m8n8.x4.trans.shared.b16 {%0,%1,%2,%3}, [%4];"
                 : "=r"(r[0]), "=r"(r[1]), "=r"(r[2]), "=r"(r[3]) : "r"(addr));
}
__device__ __forceinline__ void mma16816(float* c, const unsigned* a, const unsigned* b) {
    asm volatile("mma.sync.aligned.m16n8k16.row.col.f32.f16.f16.f32 "
                 "{%0,%1,%2,%3}, {%4,%5,%6,%7}, {%8,%9}, {%0,%1,%2,%3};"
                 : "+f"(c[0]), "+f"(c[1]), "+f"(c[2]), "+f"(c[3])
                 : "r"(a[0]), "r"(a[1]), "r"(a[2]), "r"(a[3]), "r"(b[0]), "r"(b[1]));
}

__global__ __launch_bounds__(256) void mma_gemm_kernel(
    const __half* __restrict__ A, const __half* __restrict__ B,
    __half* __restrict__ C, int M, int K) {
    __shared__ unsigned As[2][128 * A_ST];
    __shared__ unsigned Bs[2][32 * B_ST];

    int t = threadIdx.x;
    int lane = t & 31;
    int warpid = t >> 5;
    int warp_m = (warpid & 1) * 64;
    int warp_n = (warpid >> 1) * 32;
    int bx = blockIdx.x, by = blockIdx.y;

    float acc[4][4][4];
#pragma unroll
    for (int i = 0; i < 4; i++)
#pragma unroll
        for (int j = 0; j < 4; j++)
#pragma unroll
            for (int k = 0; k < 4; k++) acc[i][j][k] = 0.f;

    int tt = lane >> 3, rr = lane & 7;
    unsigned a_base0 = (unsigned)__cvta_generic_to_shared(&As[0][0]);
    unsigned b_base0 = (unsigned)__cvta_generic_to_shared(&Bs[0][0]);

    int arow = t >> 1;
    int aseg = t & 1;
    int grow = by * 128 + arow;
    bool aok = grow < M;
    const __half* Arow = A + (size_t)grow * K + aseg * 16;
    int brow = t >> 3;
    int bseg = t & 7;
    const __half* Bp = B + bx * 128 + bseg * 16;

    uint4 av0, av1, bv0, bv1;

#define LOAD_TILE(k0) do { \
        if (aok) { av0 = *(const uint4*)(Arow + (k0)); av1 = *(const uint4*)(Arow + (k0) + 8); } \
        else { av0 = make_uint4(0,0,0,0); av1 = av0; } \
        const __half* _bp = Bp + (size_t)((k0) + brow) * 256; \
        bv0 = *(const uint4*)_bp; bv1 = *(const uint4*)(_bp + 8); \
    } while (0)

#define STORE_TILE(buf) do { \
        unsigned* as = &As[buf][arow * A_ST + aseg * 8]; \
        *(uint2*)(as)     = make_uint2(av0.x, av0.y); \
        *(uint2*)(as + 2) = make_uint2(av0.z, av0.w); \
        *(uint2*)(as + 4) = make_uint2(av1.x, av1.y); \
        *(uint2*)(as + 6) = make_uint2(av1.z, av1.w); \
        unsigned* bs = &Bs[buf][brow * B_ST + bseg * 8]; \
        *(uint4*)(bs)     = bv0; \
        *(uint4*)(bs + 4) = bv1; \
    } while (0)

#define COMPUTE(buf) do { \
        unsigned a_base = a_base0 + (buf) * (128 * A_ST * 4); \
        unsigned b_base = b_base0 + (buf) * (32 * B_ST * 4); \
        _Pragma("unroll") \
        for (int ks = 0; ks < 2; ks++) { \
            int k16 = ks * 16; \
            unsigned a[4][4]; \
            _Pragma("unroll") \
            for (int mf = 0; mf < 4; mf++) { \
                int row = warp_m + mf * 16 + (tt & 1) * 8 + rr; \
                int kk = k16 + (tt >> 1) * 8; \
                ldmat4(a[mf], a_base + (unsigned)(row * (A_ST * 2) + kk) * 2); \
            } \
            unsigned b[4][2]; \
            _Pragma("unroll") \
            for (int nf2 = 0; nf2 < 2; nf2++) { \
                int row = k16 + (tt & 1) * 8 + rr; \
                int col = warp_n + nf2 * 16 + (tt >> 1) * 8; \
                unsigned rh[4]; \
                ldmat4t(rh, b_base + (unsigned)(row * (B_ST * 2) + col) * 2); \
                b[nf2 * 2][0] = rh[0]; b[nf2 * 2][1] = rh[1]; \
                b[nf2 * 2 + 1][0] = rh[2]; b[nf2 * 2 + 1][1] = rh[3]; \
            } \
            _Pragma("unroll") \
            for (int mf = 0; mf < 4; mf++) \
                _Pragma("unroll") \
                for (int nf = 0; nf < 4; nf++) \
                    mma16816(acc[mf][nf], a[mf], b[nf]); \
        } \
    } while (0)

    LOAD_TILE(0);
    STORE_TILE(0);
    __syncthreads();
    int buf = 0;
    for (int k0 = 32; k0 < K; k0 += 32) {
        LOAD_TILE(k0);
        COMPUTE(buf);
        STORE_TILE(buf ^ 1);
        __syncthreads();
        buf ^= 1;
    }
    COMPUTE(buf);

    int g = lane >> 2, tg = lane & 3;
#pragma unroll
    for (int mf = 0; mf < 4; mf++) {
#pragma unroll
        for (int nf = 0; nf < 4; nf++) {
            int col = bx * 128 + warp_n + nf * 8 + tg * 2;
            int row0 = by * 128 + warp_m + mf * 16 + g;
            int row1 = row0 + 8;
            if (row0 < M)
                *(__half2*)(C + (size_t)row0 * 256 + col) = __floats2half2_rn(acc[mf][nf][0], acc[mf][nf][1]);
            if (row1 < M)
                *(__half2*)(C + (size_t)row1 * 256 + col) = __floats2half2_rn(acc[mf][nf][2], acc[mf][nf][3]);
        }
    }
}

// ---------------- gathers (CSR, no atomics), 1 warp per segment, fp16 rows ----------------
__global__ __launch_bounds__(256) void gather_edge_kernel() {
    int seg = blockIdx.x * 8 + threadIdx.y;
    int t = threadIdx.x;
    __shared__ int idx[8][32];
    int s = g_ptr_edge[seg], en = g_ptr_edge[seg + 1];
    s = min(max(s, 0), NNZ); en = min(max(en, s), NNZ);
    float2 a0 = make_float2(0,0), a1 = make_float2(0,0), a2 = make_float2(0,0), a3 = make_float2(0,0);
    for (int base = s; base < en; base += 32) {
        int cnt = min(32, en - base);
        if (t < cnt) idx[threadIdx.y][t] = g_adj_edge[base + t];
        __syncwarp();
        for (int j = 0; j < cnt; j++) {
            const uint4* row = (const uint4*)(g_xw_h + (size_t)idx[threadIdx.y][j] * HID);
            uint4 v = row[t];
            float2 f0 = __half22float2(*(__half2*)&v.x);
            float2 f1 = __half22float2(*(__half2*)&v.y);
            float2 f2 = __half22float2(*(__half2*)&v.z);
            float2 f3 = __half22float2(*(__half2*)&v.w);
            a0.x += f0.x; a0.y += f0.y; a1.x += f1.x; a1.y += f1.y;
            a2.x += f2.x; a2.y += f2.y; a3.x += f3.x; a3.y += f3.y;
        }
        __syncwarp();
    }
    float b = g_binv[seg];
    uint4 ov;
    *(__half2*)&ov.x = __floats2half2_rn(a0.x * b, a0.y * b);
    *(__half2*)&ov.y = __floats2half2_rn(a1.x * b, a1.y * b);
    *(__half2*)&ov.z = __floats2half2_rn(a2.x * b, a2.y * b);
    *(__half2*)&ov.w = __floats2half2_rn(a3.x * b, a3.y * b);
    ((uint4*)(g_e_h + (size_t)seg * HID))[t] = ov;
}

__global__ __launch_bounds__(256) void gather_node_kernel(const float* __restrict__ bias) {
    int seg = blockIdx.x * 8 + threadIdx.y;
    int t = threadIdx.x;
    __shared__ int idx[8][32];
    int s = g_ptr_node[seg], en = g_ptr_node[seg + 1];
    s = min(max(s, 0), NNZ); en = min(max(en, s), NNZ);
    float2 a0 = make_float2(0,0), a1 = make_float2(0,0), a2 = make_float2(0,0), a3 = make_float2(0,0);
    for (int base = s; base < en; base += 32) {
        int cnt = min(32, en - base);
        if (t < cnt) idx[threadIdx.y][t] = g_adj_node[base + t];
        __syncwarp();
        for (int j = 0; j < cnt; j++) {
            const uint4* row = (const uint4*)(g_e_h + (size_t)idx[threadIdx.y][j] * HID);
            uint4 v = row[t];
            float2 f0 = __half22float2(*(__half2*)&v.x);
            float2 f1 = __half22float2(*(__half2*)&v.y);
            float2 f2 = __half22float2(*(__half2*)&v.z);
            float2 f3 = __half22float2(*(__half2*)&v.w);
            a0.x += f0.x; a0.y += f0.y; a1.x += f1.x; a1.y += f1.y;
            a2.x += f2.x; a2.y += f2.y; a3.x += f3.x; a3.y += f3.y;
        }
        __syncwarp();
    }
    float d = g_dinv[seg];
    const float4* bz = (const float4*)(bias + 8 * t);
    float4 c0 = bz[0], c1 = bz[1];
    uint4 ov;
    *(__half2*)&ov.x = __floats2half2_rn(fmaxf(a0.x * d + c0.x, 0.f), fmaxf(a0.y * d + c0.y, 0.f));
    *(__half2*)&ov.y = __floats2half2_rn(fmaxf(a1.x * d + c0.z, 0.f), fmaxf(a1.y * d + c0.w, 0.f));
    *(__half2*)&ov.z = __floats2half2_rn(fmaxf(a2.x * d + c1.x, 0.f), fmaxf(a2.y * d + c1.y, 0.f));
    *(__half2*)&ov.w = __floats2half2_rn(fmaxf(a3.x * d + c1.z, 0.f), fmaxf(a3.y * d + c1.w, 0.f));
    ((uint4*)(g_h_h + (size_t)seg * HID))[t] = ov;
}

// ---------------- pool part: 8 slices per graph, fp32 atomics into g_pooled ----------------
__global__ __launch_bounds__(256) void pool_part_kernel() {
    int g = blockIdx.x >> 3;          // graph
    int slice = blockIdx.x & 7;       // 0..7
    int t = threadIdx.x;
    int s = g_gstart[g], e = g_gstart[g + 1];
    s = min(max(s, 0), N_NODES); e = min(max(e, s), N_NODES);
    int len = e - s;
    int ls = s + (int)(((long long)len * slice) >> 3);
    int le = s + (int)(((long long)len * (slice + 1)) >> 3);
    float acc = 0.f;
    for (int i = ls; i < le; i++)
        acc += __half2float(g_h_h[(size_t)i * HID + t]);
    if (acc != 0.f || slice == 0)
        atomicAdd(&g_pooled[g * HID + t], acc);
}

// ---------------- MLP head ----------------
__global__ __launch_bounds__(256) void mlp_kernel(
    const float* __restrict__ M1, const float* __restrict__ bM1,
    const float* __restrict__ M2, const float* __restrict__ bM2,
    float* __restrict__ out) {
    int g = blockIdx.x, t = threadIdx.x;
    int s = g_gstart[g], e = g_gstart[g + 1];
    s = min(max(s, 0), N_NODES); e = min(max(e, s), N_NODES);
    __shared__ float p[HID];
    __shared__ float z[HID];
    __shared__ float red[HID];
    p[t] = g_pooled[g * HID + t] / (float)max(e - s, 1);
    __syncthreads();
    float a2 = bM1[t];
#pragma unroll 8
    for (int k = 0; k < HID; k++) a2 += p[k] * M1[k * HID + t];
    z[t] = fmaxf(a2, 0.f);
    __syncthreads();
    for (int o = 0; o < OUT_C; o++) {
        red[t] = z[t] * M2[t * OUT_C + o];
        __syncthreads();
        for (int ss = 128; ss > 0; ss >>= 1) {
            if (t < ss) red[t] += red[t + ss];
            __syncthreads();
        }
        if (t == 0) out[g * OUT_C + o] = red[0] + bM2[o];
        __syncthreads();
    }
}

// ---------------- launch ----------------
extern "C" void kernel_launch(void* const* d_in, const int* in_sizes, int n_in,
                              void* d_out, int out_size) {
    const float* x    = (const float*)d_in[0];
    const void*  ei   = d_in[1];
    const void*  batch= d_in[2];
    const float* W0   = (const float*)d_in[3];
    const float* b0   = (const float*)d_in[4];
    const float* W1   = (const float*)d_in[5];
    const float* b1   = (const float*)d_in[6];
    const float* W2   = (const float*)d_in[7];
    const float* b2   = (const float*)d_in[8];
    const float* M1   = (const float*)d_in[9];
    const float* bM1  = (const float*)d_in[10];
    const float* M2   = (const float*)d_in[11];
    const float* bM2  = (const float*)d_in[12];
    float* out = (float*)d_out;

    __half *xh = nullptr, *wh = nullptr, *xwptr = nullptr, *hh = nullptr;
    cudaGetSymbolAddress((void**)&xh,    g_x_h);
    cudaGetSymbolAddress((void**)&wh,    g_w_h);
    cudaGetSymbolAddress((void**)&xwptr, g_xw_h);
    cudaGetSymbolAddress((void**)&hh,    g_h_h);

    init_kernel<<<196, 256>>>((const unsigned int*)ei);
    setup_kernel<<<SETUP_NB, 256>>>(x, W0, W1, W2, ei, batch);
    scan_part_kernel<<<dim3(SCAN_NB, 2), 128>>>();
    scan_mid_kernel<<<1, 256>>>();
    scan_write_kernel<<<dim3(SCAN_NB, 2), 128>>>();
    fill_kernel<<<(NNZ + 255) / 256, 256>>>(ei);

    const float* bs[3] = {b0, b1, b2};
    const __half* A = xh;
    int K = IN_C;
    dim3 ggrid(2, (N_NODES + 127) / 128);
    dim3 gb(32, 8);
    for (int l = 0; l < 3; l++) {
        mma_gemm_kernel<<<ggrid, 256>>>(A, wh + (size_t)l * HID * HID, xwptr, N_NODES, K);
        gather_edge_kernel<<<N_EDGES / 8, gb>>>();
        gather_node_kernel<<<N_NODES / 8, gb>>>(bs[l]);
        A = hh;
        K = HID;
    }
    pool_part_kernel<<<N_GRAPHS * 8, 256>>>();
    mlp_kernel<<<N_GRAPHS, 256>>>(M1, bM1, M2, bM2, out);
}